// round 1
// baseline (speedup 1.0000x reference)
#include <cuda_runtime.h>
#include <cstdint>

// Problem dims
#define BB   2048      // batch
#define NN   196       // patches
#define DD   1024      // dino dim
#define DC   512       // clip dim

// Scratch (device globals: no allocation allowed)
__device__ float g_t[(size_t)BB * DD];     // tanh(txt@W^T + b), then normalized in place
__device__ float g_vsel[(size_t)BB * DD];  // selected + normalized visual rows

// ---------------------------------------------------------------------------
// Packed f32x2 FMA (full-rate fp32 on sm_103a; 3-reg FFMA is half rate)
// ---------------------------------------------------------------------------
#define FMA2(d, a, b) asm("fma.rn.f32x2 %0, %1, %2, %0;" : "+l"(d) : "l"(a), "l"(b))
#define PACKDUP(d, s) asm("mov.b64 %0, {%1, %1};" : "=l"(d) : "r"(s))

union F4U { float4 f; unsigned long long u[2]; };

// ---------------------------------------------------------------------------
// NT SGEMM: C[M,N] = A[M,K] @ B[N,K]^T    (both row-major, inner-product on K)
// Block tile 128(m) x 64(n), BK=16, 256 threads, 8x4 outputs/thread (f32x2
// pairs along m). Optional epilogue: tanh(x + bias[n]).
// ---------------------------------------------------------------------------
template <bool TANH>
__global__ __launch_bounds__(256) void sgemm_nt(
    const float* __restrict__ A, const float* __restrict__ B,
    const float* __restrict__ bias, float* __restrict__ C,
    int M, int N, int K)
{
    __shared__ float As[16][128];   // k-major
    __shared__ float Bs[16][64];    // k-major

    const int tid = threadIdx.x;
    const int bm = blockIdx.y * 128;
    const int bn = blockIdx.x * 64;
    const int tx = tid & 15;        // n dir (4 cols)
    const int ty = tid >> 4;        // m dir (8 rows)

    unsigned long long acc[4][4];   // [m-pair][n], f32x2 packed along m
    #pragma unroll
    for (int p = 0; p < 4; p++)
        #pragma unroll
        for (int j = 0; j < 4; j++) acc[p][j] = 0ull;

    // A tile loads: 128x16 floats; thread -> row tid/2, col (tid&1)*8 (+0,+4)
    const int rA = tid >> 1;
    const int cA = (tid & 1) * 8;
    // B tile loads: 64x16 floats; thread -> row tid/4, col (tid&3)*4
    const int rB = tid >> 2;
    const int cB = (tid & 3) * 4;

    const float* Aptr = A + (size_t)(bm + rA) * K + cA;
    const float* Bptr = B + (size_t)(bn + rB) * K + cB;

    for (int kt = 0; kt < K; kt += 16) {
        float4 a0 = *(const float4*)(Aptr + kt);
        float4 a1 = *(const float4*)(Aptr + kt + 4);
        float4 b0 = *(const float4*)(Bptr + kt);

        __syncthreads();
        As[cA + 0][rA] = a0.x; As[cA + 1][rA] = a0.y;
        As[cA + 2][rA] = a0.z; As[cA + 3][rA] = a0.w;
        As[cA + 4][rA] = a1.x; As[cA + 5][rA] = a1.y;
        As[cA + 6][rA] = a1.z; As[cA + 7][rA] = a1.w;
        Bs[cB + 0][rB] = b0.x; Bs[cB + 1][rB] = b0.y;
        Bs[cB + 2][rB] = b0.z; Bs[cB + 3][rB] = b0.w;
        __syncthreads();

        #pragma unroll
        for (int k = 0; k < 16; k++) {
            F4U A0, A1;
            A0.f = *(const float4*)&As[k][ty * 8];
            A1.f = *(const float4*)&As[k][ty * 8 + 4];
            float4 bv = *(const float4*)&Bs[k][tx * 4];
            unsigned long long bd0, bd1, bd2, bd3;
            PACKDUP(bd0, __float_as_uint(bv.x));
            PACKDUP(bd1, __float_as_uint(bv.y));
            PACKDUP(bd2, __float_as_uint(bv.z));
            PACKDUP(bd3, __float_as_uint(bv.w));
            FMA2(acc[0][0], A0.u[0], bd0); FMA2(acc[0][1], A0.u[0], bd1);
            FMA2(acc[0][2], A0.u[0], bd2); FMA2(acc[0][3], A0.u[0], bd3);
            FMA2(acc[1][0], A0.u[1], bd0); FMA2(acc[1][1], A0.u[1], bd1);
            FMA2(acc[1][2], A0.u[1], bd2); FMA2(acc[1][3], A0.u[1], bd3);
            FMA2(acc[2][0], A1.u[0], bd0); FMA2(acc[2][1], A1.u[0], bd1);
            FMA2(acc[2][2], A1.u[0], bd2); FMA2(acc[2][3], A1.u[0], bd3);
            FMA2(acc[3][0], A1.u[1], bd0); FMA2(acc[3][1], A1.u[1], bd1);
            FMA2(acc[3][2], A1.u[1], bd2); FMA2(acc[3][3], A1.u[1], bd3);
        }
    }

    const int n0 = bn + tx * 4;
    float4 bv4 = make_float4(0.f, 0.f, 0.f, 0.f);
    if (TANH) bv4 = *(const float4*)(bias + n0);

    #pragma unroll
    for (int p = 0; p < 4; p++) {
        const int m0 = bm + ty * 8 + p * 2;
        float lo[4], hi[4];
        #pragma unroll
        for (int j = 0; j < 4; j++) {
            lo[j] = __uint_as_float((unsigned)(acc[p][j] & 0xffffffffu));
            hi[j] = __uint_as_float((unsigned)(acc[p][j] >> 32));
        }
        if (TANH) {
            lo[0] = tanhf(lo[0] + bv4.x); lo[1] = tanhf(lo[1] + bv4.y);
            lo[2] = tanhf(lo[2] + bv4.z); lo[3] = tanhf(lo[3] + bv4.w);
            hi[0] = tanhf(hi[0] + bv4.x); hi[1] = tanhf(hi[1] + bv4.y);
            hi[2] = tanhf(hi[2] + bv4.z); hi[3] = tanhf(hi[3] + bv4.w);
        }
        *(float4*)(C + (size_t)m0 * N + n0)       = make_float4(lo[0], lo[1], lo[2], lo[3]);
        *(float4*)(C + (size_t)(m0 + 1) * N + n0) = make_float4(hi[0], hi[1], hi[2], hi[3]);
    }
}

// ---------------------------------------------------------------------------
// Per-batch: normalize t row in place, stream v[b] (196x1024), compute
// sims = (t . v_j)/||v_j||, argmax (first-index tie-break), write
// v_sel[b] = v[b, jmax] / ||v[b, jmax]||.  One block per batch element.
// ---------------------------------------------------------------------------
__global__ __launch_bounds__(256) void select_kernel(
    const float* __restrict__ vis, float* __restrict__ t, float* __restrict__ vsel)
{
    __shared__ float ts[DD];
    __shared__ float s_sim[8];
    __shared__ int   s_j[8];
    __shared__ float s_nn[8];
    __shared__ float s_scale;
    __shared__ int   s_bj;

    const int b    = blockIdx.x;
    const int tid  = threadIdx.x;
    const int lane = tid & 31;
    const int w    = tid >> 5;

    // ---- load + normalize t row (scaling by a positive const preserves argmax) ----
    float* trow = t + (size_t)b * DD;
    float4 tv = ((const float4*)trow)[tid];
    float ss = tv.x * tv.x + tv.y * tv.y + tv.z * tv.z + tv.w * tv.w;
    #pragma unroll
    for (int o = 16; o; o >>= 1) ss += __shfl_xor_sync(0xffffffffu, ss, o);
    if (lane == 0) s_nn[w] = ss;
    __syncthreads();
    if (tid == 0) {
        float tot = 0.f;
        #pragma unroll
        for (int i = 0; i < 8; i++) tot += s_nn[i];
        s_scale = 1.0f / fmaxf(sqrtf(tot), 1e-12f);
    }
    __syncthreads();
    {
        const float inv = s_scale;
        tv.x *= inv; tv.y *= inv; tv.z *= inv; tv.w *= inv;
        ((float4*)ts)[tid]   = tv;
        ((float4*)trow)[tid] = tv;   // normalized t for the final GEMM
    }
    __syncthreads();

    // ---- stream v[b], fused dot + norm^2, warp-strided over j ----
    float best = -1e30f;
    int   bj   = 0x7fffffff;
    float bnn  = 1.0f;
    const float4* tsv = (const float4*)ts;

    for (int j = w; j < NN; j += 8) {
        const float4* vr = (const float4*)(vis + ((size_t)b * NN + j) * DD);
        float dot = 0.f, nn = 0.f;
        #pragma unroll
        for (int i = 0; i < 8; i++) {
            float4 x  = vr[lane + 32 * i];
            float4 tt = tsv[lane + 32 * i];
            dot += x.x * tt.x; dot += x.y * tt.y; dot += x.z * tt.z; dot += x.w * tt.w;
            nn  += x.x * x.x;  nn  += x.y * x.y;  nn  += x.z * x.z;  nn  += x.w * x.w;
        }
        #pragma unroll
        for (int o = 16; o; o >>= 1) {
            dot += __shfl_xor_sync(0xffffffffu, dot, o);
            nn  += __shfl_xor_sync(0xffffffffu, nn, o);
        }
        const float sim = dot * rsqrtf(fmaxf(nn, 1e-24f));
        if (sim > best) { best = sim; bj = j; bnn = nn; }
    }
    if (lane == 0) { s_sim[w] = best; s_j[w] = bj; s_nn[w] = bnn; }
    __syncthreads();

    if (tid == 0) {
        float bs = s_sim[0]; int bjj = s_j[0]; float bn = s_nn[0];
        #pragma unroll
        for (int i = 1; i < 8; i++) {
            if (s_sim[i] > bs || (s_sim[i] == bs && s_j[i] < bjj)) {
                bs = s_sim[i]; bjj = s_j[i]; bn = s_nn[i];
            }
        }
        s_bj = bjj;
        s_scale = 1.0f / fmaxf(sqrtf(bn), 1e-12f);
    }
    __syncthreads();

    // ---- write normalized selected row (re-read is an L2 hit) ----
    const int   jb = s_bj;
    const float sc = s_scale;
    const float4* vrb = (const float4*)(vis + ((size_t)b * NN + jb) * DD);
    float4 x = vrb[tid];
    x.x *= sc; x.y *= sc; x.z *= sc; x.w *= sc;
    ((float4*)(vsel + (size_t)b * DD))[tid] = x;
}

// ---------------------------------------------------------------------------
// Launch
// ---------------------------------------------------------------------------
extern "C" void kernel_launch(void* const* d_in, const int* in_sizes, int n_in,
                              void* d_out, int out_size)
{
    // Identify inputs by element count (robust to ordering).
    const float* vis  = nullptr;  // 2048*196*1024
    const float* txt  = nullptr;  // 2048*512
    const float* W    = nullptr;  // 1024*512
    const float* bias = nullptr;  // 1024
    for (int i = 0; i < n_in; i++) {
        const long long s = in_sizes[i];
        if      (s == (long long)BB * NN * DD) vis  = (const float*)d_in[i];
        else if (s == (long long)BB * DC)      txt  = (const float*)d_in[i];
        else if (s == (long long)DD * DC)      W    = (const float*)d_in[i];
        else if (s == (long long)DD)           bias = (const float*)d_in[i];
    }
    float* out = (float*)d_out;

    float *t_ptr, *vsel_ptr;
    cudaGetSymbolAddress((void**)&t_ptr, g_t);
    cudaGetSymbolAddress((void**)&vsel_ptr, g_vsel);

    // K1: t = tanh(txt @ W^T + b)   [2048,1024], K=512
    {
        dim3 grid(DD / 64, BB / 128);
        sgemm_nt<true><<<grid, 256>>>(txt, W, bias, t_ptr, BB, DD, DC);
    }
    // K2: normalize t, argmax over patches, write selected normalized v rows
    select_kernel<<<BB, 256>>>(vis, t_ptr, vsel_ptr);
    // K3: out = t_norm @ vsel^T   [2048,2048], K=1024
    {
        dim3 grid(BB / 64, BB / 128);
        sgemm_nt<false><<<grid, 256>>>(t_ptr, vsel_ptr, nullptr, out, BB, BB, DD);
    }
}

// round 2
// speedup vs baseline: 1.1457x; 1.1457x over previous
#include <cuda_runtime.h>
#include <cstdint>

// Problem dims
#define BB   2048      // batch
#define NN   196       // patches
#define DD   1024      // dino dim
#define DC   512       // clip dim

// Scratch (device globals: no allocation allowed)
__device__ float g_t[(size_t)BB * DD];     // tanh(txt@W^T + b), then normalized in place
__device__ float g_vsel[(size_t)BB * DD];  // selected + normalized visual rows

// ---------------------------------------------------------------------------
// Packed f32x2 FMA (full-rate fp32 on sm_103a; 3-reg FFMA is half rate)
// ---------------------------------------------------------------------------
#define FMA2(d, a, b) asm("fma.rn.f32x2 %0, %1, %2, %0;" : "+l"(d) : "l"(a), "l"(b))
#define PACKDUP(d, s) asm("mov.b64 %0, {%1, %1};" : "=l"(d) : "r"(s))

union F4U { float4 f; unsigned long long u[2]; };

// ---------------------------------------------------------------------------
// NT SGEMM: C[M,N] = A[M,K] @ B[N,K]^T  (row-major, inner product on K)
// Block tile 128m x 128n, BK=16, 256 threads, 8x8 per thread (f32x2 packed
// along m). Double-buffered smem, conflict-free STS/LDS. Optional epilogue
// tanh(x + bias[n]).
// Requires M%128==0, N%128==0, K%16==0.
// ---------------------------------------------------------------------------
template <bool TANH>
__global__ __launch_bounds__(256) void sgemm_nt(
    const float* __restrict__ A, const float* __restrict__ B,
    const float* __restrict__ bias, float* __restrict__ C,
    int M, int N, int K)
{
    __shared__ float As[2][16][132];   // k-major, padded (STS conflict-free)
    __shared__ float Bs[2][16][132];

    const int tid = threadIdx.x;
    const int bm = blockIdx.y * 128;
    const int bn = blockIdx.x * 128;
    const int tx = tid & 15;          // n dir
    const int ty = tid >> 4;          // m dir

    // Loader mapping: each thread loads one 128-row x 16-col tile slice:
    // row r (0..127), cols c..c+3 and c+8..c+11 (c = 0 or 4).
    const int r = tid >> 1;
    const int c = (tid & 1) * 4;

    const float* Ap = A + (size_t)(bm + r) * K + c;
    const float* Bp = B + (size_t)(bn + r) * K + c;

    unsigned long long acc[4][8];     // [m-pair][n], n = {tx*4+j, 64+tx*4+j}
    #pragma unroll
    for (int p = 0; p < 4; p++)
        #pragma unroll
        for (int j = 0; j < 8; j++) acc[p][j] = 0ull;

    // ---- preload stage 0 ----
    float4 a0 = *(const float4*)(Ap);
    float4 a1 = *(const float4*)(Ap + 8);
    float4 b0 = *(const float4*)(Bp);
    float4 b1 = *(const float4*)(Bp + 8);
    {
        float va[4] = {a0.x, a0.y, a0.z, a0.w};
        float wa[4] = {a1.x, a1.y, a1.z, a1.w};
        float vb[4] = {b0.x, b0.y, b0.z, b0.w};
        float wb[4] = {b1.x, b1.y, b1.z, b1.w};
        #pragma unroll
        for (int i = 0; i < 4; i++) {
            As[0][c + i][r]     = va[i];
            As[0][c + 8 + i][r] = wa[i];
            Bs[0][c + i][r]     = vb[i];
            Bs[0][c + 8 + i][r] = wb[i];
        }
    }
    __syncthreads();

    const int nk = K >> 4;
    for (int kt = 0; kt < nk; kt++) {
        const int cur = kt & 1;

        // prefetch next stage to registers
        float4 na0, na1, nb0, nb1;
        if (kt + 1 < nk) {
            const int off = (kt + 1) * 16;
            na0 = *(const float4*)(Ap + off);
            na1 = *(const float4*)(Ap + off + 8);
            nb0 = *(const float4*)(Bp + off);
            nb1 = *(const float4*)(Bp + off + 8);
        }

        #pragma unroll
        for (int k = 0; k < 16; k++) {
            F4U Alo, Ahi;
            Alo.f = *(const float4*)&As[cur][k][ty * 8];
            Ahi.f = *(const float4*)&As[cur][k][ty * 8 + 4];
            float4 bA = *(const float4*)&Bs[cur][k][tx * 4];
            float4 bB = *(const float4*)&Bs[cur][k][64 + tx * 4];
            unsigned long long d[8];
            PACKDUP(d[0], __float_as_uint(bA.x));
            PACKDUP(d[1], __float_as_uint(bA.y));
            PACKDUP(d[2], __float_as_uint(bA.z));
            PACKDUP(d[3], __float_as_uint(bA.w));
            PACKDUP(d[4], __float_as_uint(bB.x));
            PACKDUP(d[5], __float_as_uint(bB.y));
            PACKDUP(d[6], __float_as_uint(bB.z));
            PACKDUP(d[7], __float_as_uint(bB.w));
            #pragma unroll
            for (int j = 0; j < 8; j++) {
                FMA2(acc[0][j], Alo.u[0], d[j]);
                FMA2(acc[1][j], Alo.u[1], d[j]);
                FMA2(acc[2][j], Ahi.u[0], d[j]);
                FMA2(acc[3][j], Ahi.u[1], d[j]);
            }
        }

        if (kt + 1 < nk) {
            const int nxt = cur ^ 1;
            float va[4] = {na0.x, na0.y, na0.z, na0.w};
            float wa[4] = {na1.x, na1.y, na1.z, na1.w};
            float vb[4] = {nb0.x, nb0.y, nb0.z, nb0.w};
            float wb[4] = {nb1.x, nb1.y, nb1.z, nb1.w};
            #pragma unroll
            for (int i = 0; i < 4; i++) {
                As[nxt][c + i][r]     = va[i];
                As[nxt][c + 8 + i][r] = wa[i];
                Bs[nxt][c + i][r]     = vb[i];
                Bs[nxt][c + 8 + i][r] = wb[i];
            }
            __syncthreads();
        }
    }

    // ---- epilogue ----
    const int n0 = bn + tx * 4;
    const int n1 = bn + 64 + tx * 4;
    float4 bias0 = make_float4(0.f, 0.f, 0.f, 0.f);
    float4 bias1 = make_float4(0.f, 0.f, 0.f, 0.f);
    if (TANH) {
        bias0 = *(const float4*)(bias + n0);
        bias1 = *(const float4*)(bias + n1);
    }

    #pragma unroll
    for (int p = 0; p < 4; p++) {
        const int m0 = bm + ty * 8 + p * 2;
        float lo[8], hi[8];
        #pragma unroll
        for (int j = 0; j < 8; j++) {
            lo[j] = __uint_as_float((unsigned)(acc[p][j] & 0xffffffffu));
            hi[j] = __uint_as_float((unsigned)(acc[p][j] >> 32));
        }
        if (TANH) {
            lo[0] = tanhf(lo[0] + bias0.x); lo[1] = tanhf(lo[1] + bias0.y);
            lo[2] = tanhf(lo[2] + bias0.z); lo[3] = tanhf(lo[3] + bias0.w);
            lo[4] = tanhf(lo[4] + bias1.x); lo[5] = tanhf(lo[5] + bias1.y);
            lo[6] = tanhf(lo[6] + bias1.z); lo[7] = tanhf(lo[7] + bias1.w);
            hi[0] = tanhf(hi[0] + bias0.x); hi[1] = tanhf(hi[1] + bias0.y);
            hi[2] = tanhf(hi[2] + bias0.z); hi[3] = tanhf(hi[3] + bias0.w);
            hi[4] = tanhf(hi[4] + bias1.x); hi[5] = tanhf(hi[5] + bias1.y);
            hi[6] = tanhf(hi[6] + bias1.z); hi[7] = tanhf(hi[7] + bias1.w);
        }
        *(float4*)(C + (size_t)m0 * N + n0)       = make_float4(lo[0], lo[1], lo[2], lo[3]);
        *(float4*)(C + (size_t)m0 * N + n1)       = make_float4(lo[4], lo[5], lo[6], lo[7]);
        *(float4*)(C + (size_t)(m0 + 1) * N + n0) = make_float4(hi[0], hi[1], hi[2], hi[3]);
        *(float4*)(C + (size_t)(m0 + 1) * N + n1) = make_float4(hi[4], hi[5], hi[6], hi[7]);
    }
}

// ---------------------------------------------------------------------------
// Per-batch: normalize t row in place, stream v[b] (196x1024), compute
// sims = (t . v_j)/||v_j||, argmax (first-index tie-break), write
// v_sel[b] = v[b, jmax] / ||v[b, jmax]||.  One block per batch element.
// ---------------------------------------------------------------------------
__global__ __launch_bounds__(256) void select_kernel(
    const float* __restrict__ vis, float* __restrict__ t, float* __restrict__ vsel)
{
    __shared__ float ts[DD];
    __shared__ float s_sim[8];
    __shared__ int   s_j[8];
    __shared__ float s_nn[8];
    __shared__ float s_scale;
    __shared__ int   s_bj;

    const int b    = blockIdx.x;
    const int tid  = threadIdx.x;
    const int lane = tid & 31;
    const int w    = tid >> 5;

    // ---- load + normalize t row ----
    float* trow = t + (size_t)b * DD;
    float4 tv = ((const float4*)trow)[tid];
    float ss = tv.x * tv.x + tv.y * tv.y + tv.z * tv.z + tv.w * tv.w;
    #pragma unroll
    for (int o = 16; o; o >>= 1) ss += __shfl_xor_sync(0xffffffffu, ss, o);
    if (lane == 0) s_nn[w] = ss;
    __syncthreads();
    if (tid == 0) {
        float tot = 0.f;
        #pragma unroll
        for (int i = 0; i < 8; i++) tot += s_nn[i];
        s_scale = 1.0f / fmaxf(sqrtf(tot), 1e-12f);
    }
    __syncthreads();
    {
        const float inv = s_scale;
        tv.x *= inv; tv.y *= inv; tv.z *= inv; tv.w *= inv;
        ((float4*)ts)[tid]   = tv;
        ((float4*)trow)[tid] = tv;   // normalized t for the final GEMM
    }
    __syncthreads();

    // ---- stream v[b], fused dot + norm^2, warp-strided over j ----
    float best = -1e30f;
    int   bj   = 0x7fffffff;
    float bnn  = 1.0f;
    const float4* tsv = (const float4*)ts;

    for (int j = w; j < NN; j += 8) {
        const float4* vr = (const float4*)(vis + ((size_t)b * NN + j) * DD);
        float dot = 0.f, nn = 0.f;
        #pragma unroll
        for (int i = 0; i < 8; i++) {
            float4 x  = vr[lane + 32 * i];
            float4 tt = tsv[lane + 32 * i];
            dot += x.x * tt.x; dot += x.y * tt.y; dot += x.z * tt.z; dot += x.w * tt.w;
            nn  += x.x * x.x;  nn  += x.y * x.y;  nn  += x.z * x.z;  nn  += x.w * x.w;
        }
        #pragma unroll
        for (int o = 16; o; o >>= 1) {
            dot += __shfl_xor_sync(0xffffffffu, dot, o);
            nn  += __shfl_xor_sync(0xffffffffu, nn, o);
        }
        const float sim = dot * rsqrtf(fmaxf(nn, 1e-24f));
        if (sim > best) { best = sim; bj = j; bnn = nn; }
    }
    if (lane == 0) { s_sim[w] = best; s_j[w] = bj; s_nn[w] = bnn; }
    __syncthreads();

    if (tid == 0) {
        float bs = s_sim[0]; int bjj = s_j[0]; float bn = s_nn[0];
        #pragma unroll
        for (int i = 1; i < 8; i++) {
            if (s_sim[i] > bs || (s_sim[i] == bs && s_j[i] < bjj)) {
                bs = s_sim[i]; bjj = s_j[i]; bn = s_nn[i];
            }
        }
        s_bj = bjj;
        s_scale = 1.0f / fmaxf(sqrtf(bn), 1e-12f);
    }
    __syncthreads();

    // ---- write normalized selected row (re-read is an L2 hit) ----
    const int   jb = s_bj;
    const float sc = s_scale;
    const float4* vrb = (const float4*)(vis + ((size_t)b * NN + jb) * DD);
    float4 x = vrb[tid];
    x.x *= sc; x.y *= sc; x.z *= sc; x.w *= sc;
    ((float4*)(vsel + (size_t)b * DD))[tid] = x;
}

// ---------------------------------------------------------------------------
// Launch
// ---------------------------------------------------------------------------
extern "C" void kernel_launch(void* const* d_in, const int* in_sizes, int n_in,
                              void* d_out, int out_size)
{
    const float* vis  = nullptr;  // 2048*196*1024
    const float* txt  = nullptr;  // 2048*512
    const float* W    = nullptr;  // 1024*512
    const float* bias = nullptr;  // 1024
    for (int i = 0; i < n_in; i++) {
        const long long s = in_sizes[i];
        if      (s == (long long)BB * NN * DD) vis  = (const float*)d_in[i];
        else if (s == (long long)BB * DC)      txt  = (const float*)d_in[i];
        else if (s == (long long)DD * DC)      W    = (const float*)d_in[i];
        else if (s == (long long)DD)           bias = (const float*)d_in[i];
    }
    float* out = (float*)d_out;

    float *t_ptr, *vsel_ptr;
    cudaGetSymbolAddress((void**)&t_ptr, g_t);
    cudaGetSymbolAddress((void**)&vsel_ptr, g_vsel);

    // K1: t = tanh(txt @ W^T + b)   [2048,1024], K=512
    {
        dim3 grid(DD / 128, BB / 128);
        sgemm_nt<true><<<grid, 256>>>(txt, W, bias, t_ptr, BB, DD, DC);
    }
    // K2: normalize t, argmax over patches, write selected normalized v rows
    select_kernel<<<BB, 256>>>(vis, t_ptr, vsel_ptr);
    // K3: out = t_norm @ vsel^T   [2048,2048], K=1024
    {
        dim3 grid(BB / 128, BB / 128);
        sgemm_nt<false><<<grid, 256>>>(t_ptr, vsel_ptr, nullptr, out, BB, BB, DD);
    }
}

// round 4
// speedup vs baseline: 1.4510x; 1.2665x over previous
#include <cuda_runtime.h>
#include <cuda_bf16.h>
#include <cstdint>

// Problem dims
#define BB   2048
#define NN   196
#define DD   1024
#define DC   512

// ---------------------------------------------------------------------------
// Scratch (device globals; no allocation allowed)
// ---------------------------------------------------------------------------
__device__ float         g_t[(size_t)BB * DD];                 // K1 output (fp32)
__device__ __nv_bfloat16 g_txt_hi[(size_t)BB * DC], g_txt_lo[(size_t)BB * DC];
__device__ __nv_bfloat16 g_W_hi[(size_t)DD * DC],   g_W_lo[(size_t)DD * DC];
__device__ __nv_bfloat16 g_t_hi[(size_t)BB * DD],   g_t_lo[(size_t)BB * DD];
__device__ __nv_bfloat16 g_v_hi[(size_t)BB * DD],   g_v_lo[(size_t)BB * DD];

// ---------------------------------------------------------------------------
// PTX helpers (all non-arch-specific: legal on compute_103 baseline)
// ---------------------------------------------------------------------------
__device__ __forceinline__ uint32_t smem_u32(const void* p) {
    uint32_t a;
    asm("{ .reg .u64 t; cvta.to.shared.u64 t, %1; cvt.u32.u64 %0, t; }" : "=r"(a) : "l"(p));
    return a;
}

#define CP_ASYNC16(saddr, gptr) \
    asm volatile("cp.async.cg.shared.global [%0], [%1], 16;" :: "r"(saddr), "l"(gptr))
#define CP_COMMIT() asm volatile("cp.async.commit_group;" ::: "memory")
#define CP_WAIT(n)  asm volatile("cp.async.wait_group %0;" :: "n"(n) : "memory")

#define LDSM4(r, addr) \
    asm volatile("ldmatrix.sync.aligned.m8n8.x4.shared.b16 {%0,%1,%2,%3}, [%4];" \
        : "=r"((r)[0]), "=r"((r)[1]), "=r"((r)[2]), "=r"((r)[3]) : "r"(addr))

#define MMA16816(d, a, b) \
    asm volatile("mma.sync.aligned.m16n8k16.row.col.f32.bf16.bf16.f32 " \
        "{%0,%1,%2,%3}, {%4,%5,%6,%7}, {%8,%9}, {%0,%1,%2,%3};" \
        : "+f"((d)[0]), "+f"((d)[1]), "+f"((d)[2]), "+f"((d)[3]) \
        : "r"((a)[0]), "r"((a)[1]), "r"((a)[2]), "r"((a)[3]), \
          "r"((b)[0]), "r"((b)[1]))

// ---------------------------------------------------------------------------
// Smem geometry: tiles of 128 rows x 32 halves, rows padded to 40 halves
// (80 B; m*5 mod 8 is a permutation -> LDSM conflict-free).
// ---------------------------------------------------------------------------
#define PITCH_H   40
#define PITCH_B   80
#define TILE_B    (128 * PITCH_B)      // 10240 bytes
#define SMEM_BYTES (2 * 4 * TILE_B)    // 2 stages x {Ah, Al, Bh, Bl} = 81920

// ---------------------------------------------------------------------------
// bf16-split NT GEMM via mma.sync (HMMA): C = (Ah+Al)[M,K] @ (Bh+Bl)[N,K]^T,
// fp32 accum, 3 products (hh + hl + lh). Block 128x128, BK=32, 256 threads,
// warp grid 2(m) x 4(n), warp tile 64x32. Optional tanh(x + bias[n]) epilogue.
// Requires M%128==0, N%128==0, K%32==0.
// ---------------------------------------------------------------------------
template <bool TANH>
__global__ __launch_bounds__(256) void mma_nt(
    const __nv_bfloat16* __restrict__ Ahi, const __nv_bfloat16* __restrict__ Alo,
    const __nv_bfloat16* __restrict__ Bhi, const __nv_bfloat16* __restrict__ Blo,
    const float* __restrict__ bias, float* __restrict__ C,
    int M, int N, int K)
{
    extern __shared__ char smem[];
    const int tid  = threadIdx.x;
    const int lane = tid & 31;
    const int wid  = tid >> 5;
    const int wm   = wid >> 2;       // 0..1
    const int wn   = wid & 3;        // 0..3
    const int bm   = blockIdx.y * 128;
    const int bn   = blockIdx.x * 128;
    const uint32_t sb = smem_u32(smem);

    float acc[4][4][4];
    #pragma unroll
    for (int i = 0; i < 4; i++)
        #pragma unroll
        for (int j = 0; j < 4; j++)
            #pragma unroll
            for (int k = 0; k < 4; k++) acc[i][j][k] = 0.f;

    const __nv_bfloat16* srcs[4] = { Ahi, Alo, Bhi, Blo };
    const int r0s[4] = { bm, bm, bn, bn };

    // loader: thread handles 2 x 16B chunks per tile, 4 tiles per stage
    const int lrow0 = tid >> 2;            // chunk 0 row
    const int lcc   = (tid & 3) * 16;      // byte col within 64B row

    auto prefetch = [&](int kt, int stage) {
        const int k0b = kt * 64;           // 32 halves = 64 bytes
        #pragma unroll
        for (int t = 0; t < 4; t++) {
            const uint32_t db = sb + (uint32_t)(stage * 4 + t) * TILE_B;
            const char* s = (const char*)srcs[t];
            #pragma unroll
            for (int it = 0; it < 2; it++) {
                const int row = lrow0 + it * 64;
                const uint32_t d = db + (uint32_t)row * PITCH_B + lcc;
                const char* g = s + ((size_t)(r0s[t] + row) * K) * 2 + k0b + lcc;
                CP_ASYNC16(d, g);
            }
        }
    };

    // fragment addresses (lane-dependent parts)
    const uint32_t aoff = (uint32_t)(wm * 64 + (lane & 15)) * PITCH_B + ((lane >> 4) * 16);
    const uint32_t boff = (uint32_t)(wn * 32 + (lane & 7) + ((lane & 16) ? 8 : 0)) * PITCH_B
                        + (((lane >> 3) & 1) * 16);

    const int nk = K >> 5;
    prefetch(0, 0);
    CP_COMMIT();

    for (int kt = 0; kt < nk; kt++) {
        if (kt + 1 < nk) { prefetch(kt + 1, (kt + 1) & 1); CP_COMMIT(); CP_WAIT(1); }
        else             { CP_WAIT(0); }
        __syncthreads();

        const uint32_t stg = (uint32_t)(kt & 1) * 4 * TILE_B;
        const uint32_t aAh = sb + stg + 0 * TILE_B;
        const uint32_t aAl = sb + stg + 1 * TILE_B;
        const uint32_t aBh = sb + stg + 2 * TILE_B;
        const uint32_t aBl = sb + stg + 3 * TILE_B;

        #pragma unroll
        for (int ks = 0; ks < 2; ks++) {
            uint32_t ah[4][4], al[4][4], bh[4][2], bl[4][2];
            #pragma unroll
            for (int mf = 0; mf < 4; mf++) {
                LDSM4(ah[mf], aAh + aoff + (uint32_t)mf * 16 * PITCH_B + ks * 32);
                LDSM4(al[mf], aAl + aoff + (uint32_t)mf * 16 * PITCH_B + ks * 32);
            }
            #pragma unroll
            for (int p = 0; p < 2; p++) {
                uint32_t r[4];
                LDSM4(r, aBh + boff + (uint32_t)p * 16 * PITCH_B + ks * 32);
                bh[2 * p][0] = r[0]; bh[2 * p][1] = r[1];
                bh[2 * p + 1][0] = r[2]; bh[2 * p + 1][1] = r[3];
                LDSM4(r, aBl + boff + (uint32_t)p * 16 * PITCH_B + ks * 32);
                bl[2 * p][0] = r[0]; bl[2 * p][1] = r[1];
                bl[2 * p + 1][0] = r[2]; bl[2 * p + 1][1] = r[3];
            }
            #pragma unroll
            for (int mf = 0; mf < 4; mf++)
                #pragma unroll
                for (int nf = 0; nf < 4; nf++) {
                    MMA16816(acc[mf][nf], ah[mf], bh[nf]);
                    MMA16816(acc[mf][nf], ah[mf], bl[nf]);
                    MMA16816(acc[mf][nf], al[mf], bh[nf]);
                }
        }
        __syncthreads();
    }

    // ---- epilogue: direct global stores (float2 per frag half) ----
    const int er = bm + wm * 64 + (lane >> 2);
    const int ec = bn + wn * 32 + (lane & 3) * 2;
    #pragma unroll
    for (int mf = 0; mf < 4; mf++)
        #pragma unroll
        for (int nf = 0; nf < 4; nf++) {
            const int r = er + mf * 16;
            const int c = ec + nf * 8;
            float v0 = acc[mf][nf][0], v1 = acc[mf][nf][1];
            float v2 = acc[mf][nf][2], v3 = acc[mf][nf][3];
            if (TANH) {
                const float b0 = __ldg(&bias[c]), b1 = __ldg(&bias[c + 1]);
                v0 = tanhf(v0 + b0); v1 = tanhf(v1 + b1);
                v2 = tanhf(v2 + b0); v3 = tanhf(v3 + b1);
            }
            *(float2*)&C[(size_t)r * N + c]       = make_float2(v0, v1);
            *(float2*)&C[(size_t)(r + 8) * N + c] = make_float2(v2, v3);
        }
}

// ---------------------------------------------------------------------------
// fp32 -> bf16 hi/lo split (for txt and W)
// ---------------------------------------------------------------------------
__global__ void split_kernel(const float* __restrict__ src,
                             __nv_bfloat16* __restrict__ hi,
                             __nv_bfloat16* __restrict__ lo, int n4)
{
    const int i = blockIdx.x * blockDim.x + threadIdx.x;
    if (i >= n4) return;
    float4 v = ((const float4*)src)[i];
    float x[4] = { v.x, v.y, v.z, v.w };
    __nv_bfloat16 h[4], l[4];
    #pragma unroll
    for (int j = 0; j < 4; j++) {
        h[j] = __float2bfloat16(x[j]);
        l[j] = __float2bfloat16(x[j] - __bfloat162float(h[j]));
    }
    __nv_bfloat162* H = (__nv_bfloat162*)hi;
    __nv_bfloat162* L = (__nv_bfloat162*)lo;
    H[2 * i]     = __halves2bfloat162(h[0], h[1]);
    H[2 * i + 1] = __halves2bfloat162(h[2], h[3]);
    L[2 * i]     = __halves2bfloat162(l[0], l[1]);
    L[2 * i + 1] = __halves2bfloat162(l[2], l[3]);
}

// ---------------------------------------------------------------------------
// Per-batch select: normalize t row, argmax_j (t . v_j)/||v_j||, emit bf16
// hi/lo splits of t_norm and the normalized selected v row.
// ---------------------------------------------------------------------------
__global__ __launch_bounds__(256) void select_kernel(const float* __restrict__ vis)
{
    __shared__ float ts[DD];
    __shared__ float s_sim[8];
    __shared__ int   s_j[8];
    __shared__ float s_nn[8];
    __shared__ float s_scale;
    __shared__ int   s_bj;

    const int b    = blockIdx.x;
    const int tid  = threadIdx.x;
    const int lane = tid & 31;
    const int w    = tid >> 5;

    // ---- load + normalize t row ----
    const float* trow = g_t + (size_t)b * DD;
    float4 tv = ((const float4*)trow)[tid];
    float ss = tv.x * tv.x + tv.y * tv.y + tv.z * tv.z + tv.w * tv.w;
    #pragma unroll
    for (int o = 16; o; o >>= 1) ss += __shfl_xor_sync(0xffffffffu, ss, o);
    if (lane == 0) s_nn[w] = ss;
    __syncthreads();
    if (tid == 0) {
        float tot = 0.f;
        #pragma unroll
        for (int i = 0; i < 8; i++) tot += s_nn[i];
        s_scale = 1.0f / fmaxf(sqrtf(tot), 1e-12f);
    }
    __syncthreads();
    {
        const float inv = s_scale;
        tv.x *= inv; tv.y *= inv; tv.z *= inv; tv.w *= inv;
        ((float4*)ts)[tid] = tv;
        float x[4] = { tv.x, tv.y, tv.z, tv.w };
        __nv_bfloat16 h[4], l[4];
        #pragma unroll
        for (int j = 0; j < 4; j++) {
            h[j] = __float2bfloat16(x[j]);
            l[j] = __float2bfloat16(x[j] - __bfloat162float(h[j]));
        }
        __nv_bfloat162* H = (__nv_bfloat162*)(g_t_hi + (size_t)b * DD);
        __nv_bfloat162* L = (__nv_bfloat162*)(g_t_lo + (size_t)b * DD);
        H[2 * tid]     = __halves2bfloat162(h[0], h[1]);
        H[2 * tid + 1] = __halves2bfloat162(h[2], h[3]);
        L[2 * tid]     = __halves2bfloat162(l[0], l[1]);
        L[2 * tid + 1] = __halves2bfloat162(l[2], l[3]);
    }
    __syncthreads();

    // ---- stream v[b], fused dot + norm^2, warp-strided over j ----
    float best = -1e30f;
    int   bj   = 0x7fffffff;
    float bnn  = 1.0f;
    const float4* tsv = (const float4*)ts;

    for (int j = w; j < NN; j += 8) {
        const float4* vr = (const float4*)(vis + ((size_t)b * NN + j) * DD);
        float dot = 0.f, nn = 0.f;
        #pragma unroll
        for (int i = 0; i < 8; i++) {
            float4 x  = vr[lane + 32 * i];
            float4 tt = tsv[lane + 32 * i];
            dot += x.x * tt.x; dot += x.y * tt.y; dot += x.z * tt.z; dot += x.w * tt.w;
            nn  += x.x * x.x;  nn  += x.y * x.y;  nn  += x.z * x.z;  nn  += x.w * x.w;
        }
        #pragma unroll
        for (int o = 16; o; o >>= 1) {
            dot += __shfl_xor_sync(0xffffffffu, dot, o);
            nn  += __shfl_xor_sync(0xffffffffu, nn, o);
        }
        const float sim = dot * rsqrtf(fmaxf(nn, 1e-24f));
        if (sim > best) { best = sim; bj = j; bnn = nn; }
    }
    if (lane == 0) { s_sim[w] = best; s_j[w] = bj; s_nn[w] = bnn; }
    __syncthreads();

    if (tid == 0) {
        float bs = s_sim[0]; int bjj = s_j[0]; float bn = s_nn[0];
        #pragma unroll
        for (int i = 1; i < 8; i++) {
            if (s_sim[i] > bs || (s_sim[i] == bs && s_j[i] < bjj)) {
                bs = s_sim[i]; bjj = s_j[i]; bn = s_nn[i];
            }
        }
        s_bj = bjj;
        s_scale = 1.0f / fmaxf(sqrtf(bn), 1e-12f);
    }
    __syncthreads();

    // ---- write bf16 hi/lo of normalized selected row (re-read = L2 hit) ----
    const int   jb = s_bj;
    const float sc = s_scale;
    const float4* vrb = (const float4*)(vis + ((size_t)b * NN + jb) * DD);
    float4 x4 = vrb[tid];
    float x[4] = { x4.x * sc, x4.y * sc, x4.z * sc, x4.w * sc };
    __nv_bfloat16 h[4], l[4];
    #pragma unroll
    for (int j = 0; j < 4; j++) {
        h[j] = __float2bfloat16(x[j]);
        l[j] = __float2bfloat16(x[j] - __bfloat162float(h[j]));
    }
    __nv_bfloat162* H = (__nv_bfloat162*)(g_v_hi + (size_t)b * DD);
    __nv_bfloat162* L = (__nv_bfloat162*)(g_v_lo + (size_t)b * DD);
    H[2 * tid]     = __halves2bfloat162(h[0], h[1]);
    H[2 * tid + 1] = __halves2bfloat162(h[2], h[3]);
    L[2 * tid]     = __halves2bfloat162(l[0], l[1]);
    L[2 * tid + 1] = __halves2bfloat162(l[2], l[3]);
}

// ---------------------------------------------------------------------------
// Launch
// ---------------------------------------------------------------------------
extern "C" void kernel_launch(void* const* d_in, const int* in_sizes, int n_in,
                              void* d_out, int out_size)
{
    const float* vis  = nullptr;
    const float* txt  = nullptr;
    const float* W    = nullptr;
    const float* bias = nullptr;
    for (int i = 0; i < n_in; i++) {
        const long long s = in_sizes[i];
        if      (s == (long long)BB * NN * DD) vis  = (const float*)d_in[i];
        else if (s == (long long)BB * DC)      txt  = (const float*)d_in[i];
        else if (s == (long long)DD * DC)      W    = (const float*)d_in[i];
        else if (s == (long long)DD)           bias = (const float*)d_in[i];
    }
    float* out = (float*)d_out;

    float *t_ptr;
    __nv_bfloat16 *txh, *txl, *wh, *wl, *th, *tl, *vh, *vl;
    cudaGetSymbolAddress((void**)&t_ptr, g_t);
    cudaGetSymbolAddress((void**)&txh, g_txt_hi);
    cudaGetSymbolAddress((void**)&txl, g_txt_lo);
    cudaGetSymbolAddress((void**)&wh,  g_W_hi);
    cudaGetSymbolAddress((void**)&wl,  g_W_lo);
    cudaGetSymbolAddress((void**)&th,  g_t_hi);
    cudaGetSymbolAddress((void**)&tl,  g_t_lo);
    cudaGetSymbolAddress((void**)&vh,  g_v_hi);
    cudaGetSymbolAddress((void**)&vl,  g_v_lo);

    cudaFuncSetAttribute(mma_nt<true>,  cudaFuncAttributeMaxDynamicSharedMemorySize, SMEM_BYTES);
    cudaFuncSetAttribute(mma_nt<false>, cudaFuncAttributeMaxDynamicSharedMemorySize, SMEM_BYTES);

    // Split txt and W into bf16 hi/lo
    {
        const int n4t = BB * DC / 4;
        split_kernel<<<(n4t + 255) / 256, 256>>>(txt, txh, txl, n4t);
        const int n4w = DD * DC / 4;
        split_kernel<<<(n4w + 255) / 256, 256>>>(W, wh, wl, n4w);
    }
    // K1: t = tanh(txt @ W^T + b)  [2048,1024], K=512
    {
        dim3 grid(DD / 128, BB / 128);
        mma_nt<true><<<grid, 256, SMEM_BYTES>>>(txh, txl, wh, wl, bias, t_ptr, BB, DD, DC);
    }
    // K2: normalize t, argmax over patches, emit bf16 splits
    select_kernel<<<BB, 256>>>(vis);
    // K3: out = t_norm @ v_sel^T  [2048,2048], K=1024
    {
        dim3 grid(BB / 128, BB / 128);
        mma_nt<false><<<grid, 256, SMEM_BYTES>>>(th, tl, vh, vl, nullptr, out, BB, BB, DD);
    }
}

// round 5
// speedup vs baseline: 1.6015x; 1.1037x over previous
#include <cuda_runtime.h>
#include <cuda_fp16.h>
#include <cstdint>

// Problem dims
#define BB   2048
#define NN   196
#define DD   1024
#define DC   512

// ---------------------------------------------------------------------------
// Scratch (device globals; no allocation allowed)
// ---------------------------------------------------------------------------
__device__ float  g_t[(size_t)BB * DD];                       // K1 output (fp32)
__device__ __half g_txt_hi[(size_t)BB * DC], g_txt_lo[(size_t)BB * DC];
__device__ __half g_W_hi[(size_t)DD * DC],   g_W_lo[(size_t)DD * DC];
__device__ __half g_t_h[(size_t)BB * DD];                     // t_norm, fp16
__device__ __half g_v_hi[(size_t)BB * DD],   g_v_lo[(size_t)BB * DD];

// ---------------------------------------------------------------------------
// PTX helpers (all sm_80-baseline: legal on compute_103)
// ---------------------------------------------------------------------------
__device__ __forceinline__ uint32_t smem_u32(const void* p) {
    uint32_t a;
    asm("{ .reg .u64 t; cvta.to.shared.u64 t, %1; cvt.u32.u64 %0, t; }" : "=r"(a) : "l"(p));
    return a;
}

#define CP_ASYNC16(saddr, gptr) \
    asm volatile("cp.async.cg.shared.global [%0], [%1], 16;" :: "r"(saddr), "l"(gptr))
#define CP_COMMIT() asm volatile("cp.async.commit_group;" ::: "memory")
#define CP_WAIT(n)  asm volatile("cp.async.wait_group %0;" :: "n"(n) : "memory")

#define LDSM4(r, addr) \
    asm volatile("ldmatrix.sync.aligned.m8n8.x4.shared.b16 {%0,%1,%2,%3}, [%4];" \
        : "=r"((r)[0]), "=r"((r)[1]), "=r"((r)[2]), "=r"((r)[3]) : "r"(addr))

#define MMA16816(d, a, b) \
    asm volatile("mma.sync.aligned.m16n8k16.row.col.f32.f16.f16.f32 " \
        "{%0,%1,%2,%3}, {%4,%5,%6,%7}, {%8,%9}, {%0,%1,%2,%3};" \
        : "+f"((d)[0]), "+f"((d)[1]), "+f"((d)[2]), "+f"((d)[3]) \
        : "r"((a)[0]), "r"((a)[1]), "r"((a)[2]), "r"((a)[3]), \
          "r"((b)[0]), "r"((b)[1]))

// ---------------------------------------------------------------------------
// Smem geometry: tiles of 128 rows x 32 halves, rows padded to 40 halves
// (80 B; m*5 mod 8 is a permutation -> LDSM conflict-free).
// ---------------------------------------------------------------------------
#define PITCH_B   80
#define TILE_B    (128 * PITCH_B)      // 10240 bytes

// ---------------------------------------------------------------------------
// fp16-split NT GEMM via mma.sync: C = A[M,K] @ B[N,K]^T, fp32 accumulate.
//  P==3: A = Ahi+Alo, B = Bhi+Blo, products hh + hl + lh  (err ~2^-22)
//  P==2: A = Ahi (pure fp16),  B = Bhi+Blo, products hh + hl (err ~2^-11)
// Block 128x128, BK=32, 256 threads, warp grid 2(m) x 4(n), warp tile 64x32.
// Optional tanh(x + bias[n]) epilogue.  M%128==0, N%128==0, K%32==0.
// ---------------------------------------------------------------------------
template <int P, bool TANH>
__global__ __launch_bounds__(256) void mma_nt(
    const __half* __restrict__ Ahi, const __half* __restrict__ Alo,
    const __half* __restrict__ Bhi, const __half* __restrict__ Blo,
    const float* __restrict__ bias, float* __restrict__ C,
    int M, int N, int K)
{
    constexpr int NT = (P == 3) ? 4 : 3;   // tiles per stage
    extern __shared__ char smem[];
    const int tid  = threadIdx.x;
    const int lane = tid & 31;
    const int wid  = tid >> 5;
    const int wm   = wid >> 2;       // 0..1
    const int wn   = wid & 3;        // 0..3
    const int bm   = blockIdx.y * 128;
    const int bn   = blockIdx.x * 128;
    const uint32_t sb = smem_u32(smem);

    float acc[4][4][4];
    #pragma unroll
    for (int i = 0; i < 4; i++)
        #pragma unroll
        for (int j = 0; j < 4; j++)
            #pragma unroll
            for (int k = 0; k < 4; k++) acc[i][j][k] = 0.f;

    // tile sources: [Ah, (Al), Bh, Bl]
    const __half* srcs[NT];
    int r0s[NT];
    srcs[0] = Ahi;      r0s[0] = bm;
    if (P == 3) { srcs[1] = Alo; r0s[1] = bm; }
    srcs[NT - 2] = Bhi; r0s[NT - 2] = bn;
    srcs[NT - 1] = Blo; r0s[NT - 1] = bn;

    const int lrow0 = tid >> 2;            // chunk row
    const int lcc   = (tid & 3) * 16;      // byte col within 64B row

    auto prefetch = [&](int kt, int stage) {
        const int k0b = kt * 64;           // 32 halves = 64 bytes
        #pragma unroll
        for (int t = 0; t < NT; t++) {
            const uint32_t db = sb + (uint32_t)(stage * NT + t) * TILE_B;
            const char* s = (const char*)srcs[t];
            #pragma unroll
            for (int it = 0; it < 2; it++) {
                const int row = lrow0 + it * 64;
                const uint32_t d = db + (uint32_t)row * PITCH_B + lcc;
                const char* g = s + ((size_t)(r0s[t] + row) * K) * 2 + k0b + lcc;
                CP_ASYNC16(d, g);
            }
        }
    };

    const uint32_t aoff = (uint32_t)(wm * 64 + (lane & 15)) * PITCH_B + ((lane >> 4) * 16);
    const uint32_t boff = (uint32_t)(wn * 32 + (lane & 7) + ((lane & 16) ? 8 : 0)) * PITCH_B
                        + (((lane >> 3) & 1) * 16);

    const int nk = K >> 5;
    prefetch(0, 0);
    CP_COMMIT();

    for (int kt = 0; kt < nk; kt++) {
        if (kt + 1 < nk) { prefetch(kt + 1, (kt + 1) & 1); CP_COMMIT(); CP_WAIT(1); }
        else             { CP_WAIT(0); }
        __syncthreads();

        const uint32_t stg = (uint32_t)(kt & 1) * NT * TILE_B;
        const uint32_t aAh = sb + stg + 0 * TILE_B;
        const uint32_t aAl = sb + stg + 1 * TILE_B;               // valid iff P==3
        const uint32_t aBh = sb + stg + (uint32_t)(NT - 2) * TILE_B;
        const uint32_t aBl = sb + stg + (uint32_t)(NT - 1) * TILE_B;

        #pragma unroll
        for (int ks = 0; ks < 2; ks++) {
            uint32_t ah[4][4], al[4][4], bh[4][2], bl[4][2];
            #pragma unroll
            for (int mf = 0; mf < 4; mf++) {
                LDSM4(ah[mf], aAh + aoff + (uint32_t)mf * 16 * PITCH_B + ks * 32);
                if (P == 3)
                    LDSM4(al[mf], aAl + aoff + (uint32_t)mf * 16 * PITCH_B + ks * 32);
            }
            #pragma unroll
            for (int p = 0; p < 2; p++) {
                uint32_t r[4];
                LDSM4(r, aBh + boff + (uint32_t)p * 16 * PITCH_B + ks * 32);
                bh[2 * p][0] = r[0]; bh[2 * p][1] = r[1];
                bh[2 * p + 1][0] = r[2]; bh[2 * p + 1][1] = r[3];
                LDSM4(r, aBl + boff + (uint32_t)p * 16 * PITCH_B + ks * 32);
                bl[2 * p][0] = r[0]; bl[2 * p][1] = r[1];
                bl[2 * p + 1][0] = r[2]; bl[2 * p + 1][1] = r[3];
            }
            #pragma unroll
            for (int mf = 0; mf < 4; mf++)
                #pragma unroll
                for (int nf = 0; nf < 4; nf++) {
                    MMA16816(acc[mf][nf], ah[mf], bh[nf]);
                    MMA16816(acc[mf][nf], ah[mf], bl[nf]);
                    if (P == 3) MMA16816(acc[mf][nf], al[mf], bh[nf]);
                }
        }
        __syncthreads();
    }

    // ---- epilogue: direct global stores (float2 per frag half) ----
    const int er = bm + wm * 64 + (lane >> 2);
    const int ec = bn + wn * 32 + (lane & 3) * 2;
    #pragma unroll
    for (int mf = 0; mf < 4; mf++)
        #pragma unroll
        for (int nf = 0; nf < 4; nf++) {
            const int r = er + mf * 16;
            const int c = ec + nf * 8;
            float v0 = acc[mf][nf][0], v1 = acc[mf][nf][1];
            float v2 = acc[mf][nf][2], v3 = acc[mf][nf][3];
            if (TANH) {
                const float b0 = __ldg(&bias[c]), b1 = __ldg(&bias[c + 1]);
                v0 = tanhf(v0 + b0); v1 = tanhf(v1 + b1);
                v2 = tanhf(v2 + b0); v3 = tanhf(v3 + b1);
            }
            *(float2*)&C[(size_t)r * N + c]       = make_float2(v0, v1);
            *(float2*)&C[(size_t)(r + 8) * N + c] = make_float2(v2, v3);
        }
}

// ---------------------------------------------------------------------------
// fp32 -> fp16 hi/lo split (for txt and W)
// ---------------------------------------------------------------------------
__global__ void split_kernel(const float* __restrict__ src,
                             __half* __restrict__ hi,
                             __half* __restrict__ lo, int n4)
{
    const int i = blockIdx.x * blockDim.x + threadIdx.x;
    if (i >= n4) return;
    float4 v = ((const float4*)src)[i];
    float x[4] = { v.x, v.y, v.z, v.w };
    __half h[4], l[4];
    #pragma unroll
    for (int j = 0; j < 4; j++) {
        h[j] = __float2half_rn(x[j]);
        l[j] = __float2half_rn(x[j] - __half2float(h[j]));
    }
    __half2* H = (__half2*)hi;
    __half2* L = (__half2*)lo;
    H[2 * i]     = __halves2half2(h[0], h[1]);
    H[2 * i + 1] = __halves2half2(h[2], h[3]);
    L[2 * i]     = __halves2half2(l[0], l[1]);
    L[2 * i + 1] = __halves2half2(l[2], l[3]);
}

// ---------------------------------------------------------------------------
// Per-batch select: normalize t row, argmax_j (t . v_j)/||v_j||, emit fp16
// t_norm and fp16 hi/lo split of the normalized selected v row.
// ---------------------------------------------------------------------------
__global__ __launch_bounds__(256) void select_kernel(const float* __restrict__ vis)
{
    __shared__ float ts[DD];
    __shared__ float s_sim[8];
    __shared__ int   s_j[8];
    __shared__ float s_nn[8];
    __shared__ float s_scale;
    __shared__ int   s_bj;

    const int b    = blockIdx.x;
    const int tid  = threadIdx.x;
    const int lane = tid & 31;
    const int w    = tid >> 5;

    // ---- load + normalize t row ----
    const float* trow = g_t + (size_t)b * DD;
    float4 tv = ((const float4*)trow)[tid];
    float ss = tv.x * tv.x + tv.y * tv.y + tv.z * tv.z + tv.w * tv.w;
    #pragma unroll
    for (int o = 16; o; o >>= 1) ss += __shfl_xor_sync(0xffffffffu, ss, o);
    if (lane == 0) s_nn[w] = ss;
    __syncthreads();
    if (tid == 0) {
        float tot = 0.f;
        #pragma unroll
        for (int i = 0; i < 8; i++) tot += s_nn[i];
        s_scale = 1.0f / fmaxf(sqrtf(tot), 1e-12f);
    }
    __syncthreads();
    {
        const float inv = s_scale;
        tv.x *= inv; tv.y *= inv; tv.z *= inv; tv.w *= inv;
        ((float4*)ts)[tid] = tv;
        __half2* H = (__half2*)(g_t_h + (size_t)b * DD);
        H[2 * tid]     = __halves2half2(__float2half_rn(tv.x), __float2half_rn(tv.y));
        H[2 * tid + 1] = __halves2half2(__float2half_rn(tv.z), __float2half_rn(tv.w));
    }
    __syncthreads();

    // ---- stream v[b] (evict-first), fused dot + norm^2, warp-strided ----
    float best = -1e30f;
    int   bj   = 0x7fffffff;
    float bnn  = 1.0f;
    const float4* tsv = (const float4*)ts;

    for (int j = w; j < NN; j += 8) {
        const float4* vr = (const float4*)(vis + ((size_t)b * NN + j) * DD);
        float dot = 0.f, nn = 0.f;
        #pragma unroll
        for (int i = 0; i < 8; i++) {
            float4 x  = __ldcs(&vr[lane + 32 * i]);
            float4 tt = tsv[lane + 32 * i];
            dot += x.x * tt.x; dot += x.y * tt.y; dot += x.z * tt.z; dot += x.w * tt.w;
            nn  += x.x * x.x;  nn  += x.y * x.y;  nn  += x.z * x.z;  nn  += x.w * x.w;
        }
        #pragma unroll
        for (int o = 16; o; o >>= 1) {
            dot += __shfl_xor_sync(0xffffffffu, dot, o);
            nn  += __shfl_xor_sync(0xffffffffu, nn, o);
        }
        const float sim = dot * rsqrtf(fmaxf(nn, 1e-24f));
        if (sim > best) { best = sim; bj = j; bnn = nn; }
    }
    if (lane == 0) { s_sim[w] = best; s_j[w] = bj; s_nn[w] = bnn; }
    __syncthreads();

    if (tid == 0) {
        float bs = s_sim[0]; int bjj = s_j[0]; float bn = s_nn[0];
        #pragma unroll
        for (int i = 1; i < 8; i++) {
            if (s_sim[i] > bs || (s_sim[i] == bs && s_j[i] < bjj)) {
                bs = s_sim[i]; bjj = s_j[i]; bn = s_nn[i];
            }
        }
        s_bj = bjj;
        s_scale = 1.0f / fmaxf(sqrtf(bn), 1e-12f);
    }
    __syncthreads();

    // ---- write fp16 hi/lo of normalized selected row (re-read = L2 hit) ----
    const int   jb = s_bj;
    const float sc = s_scale;
    const float4* vrb = (const float4*)(vis + ((size_t)b * NN + jb) * DD);
    float4 x4 = vrb[tid];
    float x[4] = { x4.x * sc, x4.y * sc, x4.z * sc, x4.w * sc };
    __half h[4], l[4];
    #pragma unroll
    for (int j = 0; j < 4; j++) {
        h[j] = __float2half_rn(x[j]);
        l[j] = __float2half_rn(x[j] - __half2float(h[j]));
    }
    __half2* H = (__half2*)(g_v_hi + (size_t)b * DD);
    __half2* L = (__half2*)(g_v_lo + (size_t)b * DD);
    H[2 * tid]     = __halves2half2(h[0], h[1]);
    H[2 * tid + 1] = __halves2half2(h[2], h[3]);
    L[2 * tid]     = __halves2half2(l[0], l[1]);
    L[2 * tid + 1] = __halves2half2(l[2], l[3]);
}

// ---------------------------------------------------------------------------
// Launch
// ---------------------------------------------------------------------------
extern "C" void kernel_launch(void* const* d_in, const int* in_sizes, int n_in,
                              void* d_out, int out_size)
{
    const float* vis  = nullptr;
    const float* txt  = nullptr;
    const float* W    = nullptr;
    const float* bias = nullptr;
    for (int i = 0; i < n_in; i++) {
        const long long s = in_sizes[i];
        if      (s == (long long)BB * NN * DD) vis  = (const float*)d_in[i];
        else if (s == (long long)BB * DC)      txt  = (const float*)d_in[i];
        else if (s == (long long)DD * DC)      W    = (const float*)d_in[i];
        else if (s == (long long)DD)           bias = (const float*)d_in[i];
    }
    float* out = (float*)d_out;

    float *t_ptr;
    __half *txh, *txl, *wh, *wl, *th, *vh, *vl;
    cudaGetSymbolAddress((void**)&t_ptr, g_t);
    cudaGetSymbolAddress((void**)&txh, g_txt_hi);
    cudaGetSymbolAddress((void**)&txl, g_txt_lo);
    cudaGetSymbolAddress((void**)&wh,  g_W_hi);
    cudaGetSymbolAddress((void**)&wl,  g_W_lo);
    cudaGetSymbolAddress((void**)&th,  g_t_h);
    cudaGetSymbolAddress((void**)&vh,  g_v_hi);
    cudaGetSymbolAddress((void**)&vl,  g_v_lo);

    const int smem3 = 2 * 4 * TILE_B;   // 81920
    const int smem2 = 2 * 3 * TILE_B;   // 61440
    cudaFuncSetAttribute(mma_nt<3, true>,  cudaFuncAttributeMaxDynamicSharedMemorySize, smem3);
    cudaFuncSetAttribute(mma_nt<2, false>, cudaFuncAttributeMaxDynamicSharedMemorySize, smem2);

    // Split txt and W into fp16 hi/lo
    {
        const int n4t = BB * DC / 4;
        split_kernel<<<(n4t + 255) / 256, 256>>>(txt, txh, txl, n4t);
        const int n4w = DD * DC / 4;
        split_kernel<<<(n4w + 255) / 256, 256>>>(W, wh, wl, n4w);
    }
    // K1: t = tanh(txt @ W^T + b)  [2048,1024], K=512  (3-product: err ~2^-22)
    {
        dim3 grid(DD / 128, BB / 128);
        mma_nt<3, true><<<grid, 256, smem3>>>(txh, txl, wh, wl, bias, t_ptr, BB, DD, DC);
    }
    // K2: normalize t, argmax over patches, emit fp16 operands for K3
    select_kernel<<<BB, 256>>>(vis);
    // K3: out = t_norm @ v_sel^T  [2048,2048], K=1024  (2-product: err ~2^-11 global ~3e-4)
    {
        dim3 grid(BB / 128, BB / 128);
        mma_nt<2, false><<<grid, 256, smem2>>>(th, nullptr, vh, vl, nullptr, out, BB, BB, DD);
    }
}

// round 6
// speedup vs baseline: 1.7271x; 1.0784x over previous
#include <cuda_runtime.h>
#include <cuda_fp16.h>
#include <cstdint>

// Problem dims
#define BB   2048
#define NN   196
#define DD   1024
#define DC   512

// ---------------------------------------------------------------------------
// Scratch (device globals; no allocation allowed)
// ---------------------------------------------------------------------------
__device__ float  g_t[(size_t)BB * DD];                       // K1 output (fp32)
__device__ __half g_txt_hi[(size_t)BB * DC], g_txt_lo[(size_t)BB * DC];
__device__ __half g_W_hi[(size_t)DD * DC],   g_W_lo[(size_t)DD * DC];
__device__ __half g_t_h[(size_t)BB * DD];                     // t_norm, fp16
__device__ __half g_v_h[(size_t)BB * DD];                     // v_sel_norm, fp16

// ---------------------------------------------------------------------------
// PTX helpers (all sm_80-baseline: legal on compute_103)
// ---------------------------------------------------------------------------
__device__ __forceinline__ uint32_t smem_u32(const void* p) {
    uint32_t a;
    asm("{ .reg .u64 t; cvta.to.shared.u64 t, %1; cvt.u32.u64 %0, t; }" : "=r"(a) : "l"(p));
    return a;
}

#define CP_ASYNC16(saddr, gptr) \
    asm volatile("cp.async.cg.shared.global [%0], [%1], 16;" :: "r"(saddr), "l"(gptr))
#define CP_COMMIT() asm volatile("cp.async.commit_group;" ::: "memory")
#define CP_WAIT(n)  asm volatile("cp.async.wait_group %0;" :: "n"(n) : "memory")

#define LDSM4(r, addr) \
    asm volatile("ldmatrix.sync.aligned.m8n8.x4.shared.b16 {%0,%1,%2,%3}, [%4];" \
        : "=r"((r)[0]), "=r"((r)[1]), "=r"((r)[2]), "=r"((r)[3]) : "r"(addr))

#define MMA16816(d, a, b) \
    asm volatile("mma.sync.aligned.m16n8k16.row.col.f32.f16.f16.f32 " \
        "{%0,%1,%2,%3}, {%4,%5,%6,%7}, {%8,%9}, {%0,%1,%2,%3};" \
        : "+f"((d)[0]), "+f"((d)[1]), "+f"((d)[2]), "+f"((d)[3]) \
        : "r"((a)[0]), "r"((a)[1]), "r"((a)[2]), "r"((a)[3]), \
          "r"((b)[0]), "r"((b)[1]))

// ---------------------------------------------------------------------------
// Smem geometry: tiles of 128 rows x 32 halves, rows padded to 40 halves
// (80 B; m*5 mod 8 is a permutation -> LDSM conflict-free).
// ---------------------------------------------------------------------------
#define PITCH_B   80
#define TILE_B    (128 * PITCH_B)      // 10240 bytes

// ---------------------------------------------------------------------------
// fp16-split NT GEMM via mma.sync: C = A[M,K] @ B[N,K]^T, fp32 accumulate.
//  SPLIT==1: A = Ahi+Alo, B = Bhi+Blo, products hh + hl + lh (err ~2^-22)
//  SPLIT==0: A = Ahi, B = Bhi, single product (err ~2^-11)
// Block 128x128, BK=32, 256 threads, warp grid 2(m) x 4(n), warp tile 64x32.
// Optional tanh(x + bias[n]) epilogue.  M%128==0, N%128==0, K%32==0.
// ---------------------------------------------------------------------------
template <bool SPLIT, bool TANH>
__global__ __launch_bounds__(256) void mma_nt(
    const __half* __restrict__ Ahi, const __half* __restrict__ Alo,
    const __half* __restrict__ Bhi, const __half* __restrict__ Blo,
    const float* __restrict__ bias, float* __restrict__ C,
    int M, int N, int K)
{
    constexpr int NT = SPLIT ? 4 : 2;   // tiles per stage
    extern __shared__ char smem[];
    const int tid  = threadIdx.x;
    const int lane = tid & 31;
    const int wid  = tid >> 5;
    const int wm   = wid >> 2;       // 0..1
    const int wn   = wid & 3;        // 0..3
    const int bm   = blockIdx.y * 128;
    const int bn   = blockIdx.x * 128;
    const uint32_t sb = smem_u32(smem);

    float acc[4][4][4];
    #pragma unroll
    for (int i = 0; i < 4; i++)
        #pragma unroll
        for (int j = 0; j < 4; j++)
            #pragma unroll
            for (int k = 0; k < 4; k++) acc[i][j][k] = 0.f;

    // tile sources: SPLIT ? [Ah, Al, Bh, Bl] : [Ah, Bh]
    const __half* srcs[NT];
    int r0s[NT];
    srcs[0] = Ahi;      r0s[0] = bm;
    if (SPLIT) {
        srcs[1] = Alo;  r0s[1] = bm;
        srcs[2] = Bhi;  r0s[2] = bn;
        srcs[3] = Blo;  r0s[3] = bn;
    } else {
        srcs[1] = Bhi;  r0s[1] = bn;
    }

    const int lrow0 = tid >> 2;            // chunk row
    const int lcc   = (tid & 3) * 16;      // byte col within 64B row

    auto prefetch = [&](int kt, int stage) {
        const int k0b = kt * 64;           // 32 halves = 64 bytes
        #pragma unroll
        for (int t = 0; t < NT; t++) {
            const uint32_t db = sb + (uint32_t)(stage * NT + t) * TILE_B;
            const char* s = (const char*)srcs[t];
            #pragma unroll
            for (int it = 0; it < 2; it++) {
                const int row = lrow0 + it * 64;
                const uint32_t d = db + (uint32_t)row * PITCH_B + lcc;
                const char* g = s + ((size_t)(r0s[t] + row) * K) * 2 + k0b + lcc;
                CP_ASYNC16(d, g);
            }
        }
    };

    const uint32_t aoff = (uint32_t)(wm * 64 + (lane & 15)) * PITCH_B + ((lane >> 4) * 16);
    const uint32_t boff = (uint32_t)(wn * 32 + (lane & 7) + ((lane & 16) ? 8 : 0)) * PITCH_B
                        + (((lane >> 3) & 1) * 16);

    const int nk = K >> 5;
    prefetch(0, 0);
    CP_COMMIT();

    for (int kt = 0; kt < nk; kt++) {
        if (kt + 1 < nk) { prefetch(kt + 1, (kt + 1) & 1); CP_COMMIT(); CP_WAIT(1); }
        else             { CP_WAIT(0); }
        __syncthreads();

        const uint32_t stg = (uint32_t)(kt & 1) * NT * TILE_B;
        const uint32_t aAh = sb + stg + 0 * TILE_B;
        const uint32_t aAl = sb + stg + 1 * TILE_B;                   // SPLIT only
        const uint32_t aBh = sb + stg + (uint32_t)(SPLIT ? 2 : 1) * TILE_B;
        const uint32_t aBl = sb + stg + 3 * TILE_B;                   // SPLIT only

        #pragma unroll
        for (int ks = 0; ks < 2; ks++) {
            uint32_t ah[4][4], al[4][4], bh[4][2], bl[4][2];
            #pragma unroll
            for (int mf = 0; mf < 4; mf++) {
                LDSM4(ah[mf], aAh + aoff + (uint32_t)mf * 16 * PITCH_B + ks * 32);
                if (SPLIT)
                    LDSM4(al[mf], aAl + aoff + (uint32_t)mf * 16 * PITCH_B + ks * 32);
            }
            #pragma unroll
            for (int p = 0; p < 2; p++) {
                uint32_t r[4];
                LDSM4(r, aBh + boff + (uint32_t)p * 16 * PITCH_B + ks * 32);
                bh[2 * p][0] = r[0]; bh[2 * p][1] = r[1];
                bh[2 * p + 1][0] = r[2]; bh[2 * p + 1][1] = r[3];
                if (SPLIT) {
                    LDSM4(r, aBl + boff + (uint32_t)p * 16 * PITCH_B + ks * 32);
                    bl[2 * p][0] = r[0]; bl[2 * p][1] = r[1];
                    bl[2 * p + 1][0] = r[2]; bl[2 * p + 1][1] = r[3];
                }
            }
            #pragma unroll
            for (int mf = 0; mf < 4; mf++)
                #pragma unroll
                for (int nf = 0; nf < 4; nf++) {
                    MMA16816(acc[mf][nf], ah[mf], bh[nf]);
                    if (SPLIT) {
                        MMA16816(acc[mf][nf], ah[mf], bl[nf]);
                        MMA16816(acc[mf][nf], al[mf], bh[nf]);
                    }
                }
        }
        __syncthreads();
    }

    // ---- epilogue: direct global stores (float2 per frag half) ----
    const int er = bm + wm * 64 + (lane >> 2);
    const int ec = bn + wn * 32 + (lane & 3) * 2;
    #pragma unroll
    for (int mf = 0; mf < 4; mf++)
        #pragma unroll
        for (int nf = 0; nf < 4; nf++) {
            const int r = er + mf * 16;
            const int c = ec + nf * 8;
            float v0 = acc[mf][nf][0], v1 = acc[mf][nf][1];
            float v2 = acc[mf][nf][2], v3 = acc[mf][nf][3];
            if (TANH) {
                const float b0 = __ldg(&bias[c]), b1 = __ldg(&bias[c + 1]);
                v0 = tanhf(v0 + b0); v1 = tanhf(v1 + b1);
                v2 = tanhf(v2 + b0); v3 = tanhf(v3 + b1);
            }
            *(float2*)&C[(size_t)r * N + c]       = make_float2(v0, v1);
            *(float2*)&C[(size_t)(r + 8) * N + c] = make_float2(v2, v3);
        }
}

// ---------------------------------------------------------------------------
// fp32 -> fp16 hi/lo split (for txt and W)
// ---------------------------------------------------------------------------
__global__ void split_kernel(const float* __restrict__ src,
                             __half* __restrict__ hi,
                             __half* __restrict__ lo, int n4)
{
    const int i = blockIdx.x * blockDim.x + threadIdx.x;
    if (i >= n4) return;
    float4 v = ((const float4*)src)[i];
    float x[4] = { v.x, v.y, v.z, v.w };
    __half h[4], l[4];
    #pragma unroll
    for (int j = 0; j < 4; j++) {
        h[j] = __float2half_rn(x[j]);
        l[j] = __float2half_rn(x[j] - __half2float(h[j]));
    }
    __half2* H = (__half2*)hi;
    __half2* L = (__half2*)lo;
    H[2 * i]     = __halves2half2(h[0], h[1]);
    H[2 * i + 1] = __halves2half2(h[2], h[3]);
    L[2 * i]     = __halves2half2(l[0], l[1]);
    L[2 * i + 1] = __halves2half2(l[2], l[3]);
}

// ---------------------------------------------------------------------------
// Per-batch select: normalize t row, argmax_j (t . v_j)/||v_j|| (pure fp32 —
// no selection-flip risk), emit fp16 t_norm and fp16 v_sel_norm.
// ---------------------------------------------------------------------------
__global__ __launch_bounds__(256) void select_kernel(const float* __restrict__ vis)
{
    __shared__ float ts[DD];
    __shared__ float s_sim[8];
    __shared__ int   s_j[8];
    __shared__ float s_nn[8];
    __shared__ float s_scale;
    __shared__ int   s_bj;

    const int b    = blockIdx.x;
    const int tid  = threadIdx.x;
    const int lane = tid & 31;
    const int w    = tid >> 5;

    // ---- load + normalize t row ----
    const float* trow = g_t + (size_t)b * DD;
    float4 tv = ((const float4*)trow)[tid];
    float ss = tv.x * tv.x + tv.y * tv.y + tv.z * tv.z + tv.w * tv.w;
    #pragma unroll
    for (int o = 16; o; o >>= 1) ss += __shfl_xor_sync(0xffffffffu, ss, o);
    if (lane == 0) s_nn[w] = ss;
    __syncthreads();
    if (tid == 0) {
        float tot = 0.f;
        #pragma unroll
        for (int i = 0; i < 8; i++) tot += s_nn[i];
        s_scale = 1.0f / fmaxf(sqrtf(tot), 1e-12f);
    }
    __syncthreads();
    {
        const float inv = s_scale;
        tv.x *= inv; tv.y *= inv; tv.z *= inv; tv.w *= inv;
        ((float4*)ts)[tid] = tv;
        __half2* H = (__half2*)(g_t_h + (size_t)b * DD);
        H[2 * tid]     = __halves2half2(__float2half_rn(tv.x), __float2half_rn(tv.y));
        H[2 * tid + 1] = __halves2half2(__float2half_rn(tv.z), __float2half_rn(tv.w));
    }
    __syncthreads();

    // ---- stream v[b] (evict-first), fused dot + norm^2, warp-strided ----
    float best = -1e30f;
    int   bj   = 0x7fffffff;
    float bnn  = 1.0f;
    const float4* tsv = (const float4*)ts;

    for (int j = w; j < NN; j += 8) {
        const float4* vr = (const float4*)(vis + ((size_t)b * NN + j) * DD);
        float dot = 0.f, nn = 0.f;
        #pragma unroll
        for (int i = 0; i < 8; i++) {
            float4 x  = __ldcs(&vr[lane + 32 * i]);
            float4 tt = tsv[lane + 32 * i];
            dot += x.x * tt.x; dot += x.y * tt.y; dot += x.z * tt.z; dot += x.w * tt.w;
            nn  += x.x * x.x;  nn  += x.y * x.y;  nn  += x.z * x.z;  nn  += x.w * x.w;
        }
        #pragma unroll
        for (int o = 16; o; o >>= 1) {
            dot += __shfl_xor_sync(0xffffffffu, dot, o);
            nn  += __shfl_xor_sync(0xffffffffu, nn, o);
        }
        const float sim = dot * rsqrtf(fmaxf(nn, 1e-24f));
        if (sim > best) { best = sim; bj = j; bnn = nn; }
    }
    if (lane == 0) { s_sim[w] = best; s_j[w] = bj; s_nn[w] = bnn; }
    __syncthreads();

    if (tid == 0) {
        float bs = s_sim[0]; int bjj = s_j[0]; float bn = s_nn[0];
        #pragma unroll
        for (int i = 1; i < 8; i++) {
            if (s_sim[i] > bs || (s_sim[i] == bs && s_j[i] < bjj)) {
                bs = s_sim[i]; bjj = s_j[i]; bn = s_nn[i];
            }
        }
        s_bj = bjj;
        s_scale = 1.0f / fmaxf(sqrtf(bn), 1e-12f);
    }
    __syncthreads();

    // ---- write fp16 normalized selected row (re-read = L2 hit) ----
    const int   jb = s_bj;
    const float sc = s_scale;
    const float4* vrb = (const float4*)(vis + ((size_t)b * NN + jb) * DD);
    float4 x4 = vrb[tid];
    __half2* H = (__half2*)(g_v_h + (size_t)b * DD);
    H[2 * tid]     = __halves2half2(__float2half_rn(x4.x * sc), __float2half_rn(x4.y * sc));
    H[2 * tid + 1] = __halves2half2(__float2half_rn(x4.z * sc), __float2half_rn(x4.w * sc));
}

// ---------------------------------------------------------------------------
// Launch
// ---------------------------------------------------------------------------
extern "C" void kernel_launch(void* const* d_in, const int* in_sizes, int n_in,
                              void* d_out, int out_size)
{
    const float* vis  = nullptr;
    const float* txt  = nullptr;
    const float* W    = nullptr;
    const float* bias = nullptr;
    for (int i = 0; i < n_in; i++) {
        const long long s = in_sizes[i];
        if      (s == (long long)BB * NN * DD) vis  = (const float*)d_in[i];
        else if (s == (long long)BB * DC)      txt  = (const float*)d_in[i];
        else if (s == (long long)DD * DC)      W    = (const float*)d_in[i];
        else if (s == (long long)DD)           bias = (const float*)d_in[i];
    }
    float* out = (float*)d_out;

    float *t_ptr;
    __half *txh, *txl, *wh, *wl, *th, *vh;
    cudaGetSymbolAddress((void**)&t_ptr, g_t);
    cudaGetSymbolAddress((void**)&txh, g_txt_hi);
    cudaGetSymbolAddress((void**)&txl, g_txt_lo);
    cudaGetSymbolAddress((void**)&wh,  g_W_hi);
    cudaGetSymbolAddress((void**)&wl,  g_W_lo);
    cudaGetSymbolAddress((void**)&th,  g_t_h);
    cudaGetSymbolAddress((void**)&vh,  g_v_h);

    const int smem3 = 2 * 4 * TILE_B;   // 81920
    const int smem1 = 2 * 2 * TILE_B;   // 40960
    cudaFuncSetAttribute(mma_nt<true, true>,   cudaFuncAttributeMaxDynamicSharedMemorySize, smem3);
    cudaFuncSetAttribute(mma_nt<false, false>, cudaFuncAttributeMaxDynamicSharedMemorySize, smem1);

    // Split txt and W into fp16 hi/lo
    {
        const int n4t = BB * DC / 4;
        split_kernel<<<(n4t + 255) / 256, 256>>>(txt, txh, txl, n4t);
        const int n4w = DD * DC / 4;
        split_kernel<<<(n4w + 255) / 256, 256>>>(W, wh, wl, n4w);
    }
    // K1: t = tanh(txt @ W^T + b)  [2048,1024], K=512  (3-product: err ~2^-22)
    {
        dim3 grid(DD / 128, BB / 128);
        mma_nt<true, true><<<grid, 256, smem3>>>(txh, txl, wh, wl, bias, t_ptr, BB, DD, DC);
    }
    // K2: normalize t, fp32 argmax over patches, emit fp16 operands for K3
    select_kernel<<<BB, 256>>>(vis);
    // K3: out = t_norm @ v_sel^T  [2048,2048], K=1024  (1-product: err ~3e-4 global)
    {
        dim3 grid(BB / 128, BB / 128);
        mma_nt<false, false><<<grid, 256, smem1>>>(th, nullptr, vh, nullptr, nullptr, out, BB, BB, DD);
    }
}

// round 7
// speedup vs baseline: 1.7709x; 1.0254x over previous
#include <cuda_runtime.h>
#include <cuda_fp16.h>
#include <cstdint>

// Problem dims
#define BB   2048
#define NN   196
#define DD   1024
#define DC   512

// ---------------------------------------------------------------------------
// Scratch (device globals; no allocation allowed)
// ---------------------------------------------------------------------------
__device__ float  g_t[(size_t)BB * DD];     // K1 output (fp32)
__device__ __half g_t_h[(size_t)BB * DD];   // t_norm, fp16
__device__ __half g_v_h[(size_t)BB * DD];   // v_sel_norm, fp16

// ---------------------------------------------------------------------------
// PTX helpers (all sm_80-baseline: legal on compute_103)
// ---------------------------------------------------------------------------
__device__ __forceinline__ uint32_t smem_u32(const void* p) {
    uint32_t a;
    asm("{ .reg .u64 t; cvta.to.shared.u64 t, %1; cvt.u32.u64 %0, t; }" : "=r"(a) : "l"(p));
    return a;
}

#define CP_ASYNC16(saddr, gptr) \
    asm volatile("cp.async.cg.shared.global [%0], [%1], 16;" :: "r"(saddr), "l"(gptr))
#define CP_COMMIT() asm volatile("cp.async.commit_group;" ::: "memory")
#define CP_WAIT(n)  asm volatile("cp.async.wait_group %0;" :: "n"(n) : "memory")

#define LDSM4(r, addr) \
    asm volatile("ldmatrix.sync.aligned.m8n8.x4.shared.b16 {%0,%1,%2,%3}, [%4];" \
        : "=r"((r)[0]), "=r"((r)[1]), "=r"((r)[2]), "=r"((r)[3]) : "r"(addr))

#define MMA16816(d, a, b) \
    asm volatile("mma.sync.aligned.m16n8k16.row.col.f32.f16.f16.f32 " \
        "{%0,%1,%2,%3}, {%4,%5,%6,%7}, {%8,%9}, {%0,%1,%2,%3};" \
        : "+f"((d)[0]), "+f"((d)[1]), "+f"((d)[2]), "+f"((d)[3]) \
        : "r"((a)[0]), "r"((a)[1]), "r"((a)[2]), "r"((a)[3]), \
          "r"((b)[0]), "r"((b)[1]))

__device__ __forceinline__ unsigned packh(__half a, __half b) {
    __half2 t = __halves2half2(a, b);
    return *reinterpret_cast<unsigned*>(&t);
}

// ---------------------------------------------------------------------------
// Smem geometry: tiles of 128 rows x 32 halves, rows padded to 40 halves
// (80 B; m*5 mod 8 is a permutation -> LDSM conflict-free).
// ---------------------------------------------------------------------------
#define PITCH_B   80
#define TILE_B    (128 * PITCH_B)      // 10240 bytes

// ===========================================================================
// K1: fused-split fp32-input NT GEMM, 3-product fp16 split (err ~2^-22),
// tanh(x + bias) epilogue.  C[M,N] = tanh(A[M,K] @ B[N,K]^T + bias).
// Loader: LDG fp32 -> split to hi/lo fp16 in regs -> STS (double-buffered).
// Block 128x128, BK=32, 256 threads, warp grid 2x4, warp tile 64x32.
// ===========================================================================
__global__ __launch_bounds__(256) void mma_nt_f32(
    const float* __restrict__ A, const float* __restrict__ B,
    const float* __restrict__ bias, float* __restrict__ C,
    int M, int N, int K)
{
    extern __shared__ char smem[];
    const int tid  = threadIdx.x;
    const int lane = tid & 31;
    const int wid  = tid >> 5;
    const int wm   = wid >> 2;
    const int wn   = wid & 3;
    const int bm   = blockIdx.y * 128;
    const int bn   = blockIdx.x * 128;
    const uint32_t sb = smem_u32(smem);

    float acc[4][4][4];
    #pragma unroll
    for (int i = 0; i < 4; i++)
        #pragma unroll
        for (int j = 0; j < 4; j++)
            #pragma unroll
            for (int k = 0; k < 4; k++) acc[i][j][k] = 0.f;

    // loader mapping: row = tid/2 (0..127), half = tid&1 -> k-cols half*16..+15
    const int lrow = tid >> 1;
    const int lhal = tid & 1;
    const float* Ap = A + (size_t)(bm + lrow) * K + lhal * 16;
    const float* Bp = B + (size_t)(bn + lrow) * K + lhal * 16;

    float4 ra[4], rb[4];
    auto ldg_stage = [&](int kt) {
        const int k0 = kt * 32;
        #pragma unroll
        for (int q = 0; q < 4; q++) {
            ra[q] = *(const float4*)(Ap + k0 + q * 4);
            rb[q] = *(const float4*)(Bp + k0 + q * 4);
        }
    };
    // tiles per stage: [Ah, Al, Bh, Bl]
    const uint32_t soff = (uint32_t)lrow * PITCH_B + (uint32_t)lhal * 32;
    auto sts_stage = [&](int stage) {
        const uint32_t base = (uint32_t)stage * 4 * TILE_B;
        float fa[16], fb[16];
        #pragma unroll
        for (int q = 0; q < 4; q++) {
            fa[4*q+0] = ra[q].x; fa[4*q+1] = ra[q].y; fa[4*q+2] = ra[q].z; fa[4*q+3] = ra[q].w;
            fb[4*q+0] = rb[q].x; fb[4*q+1] = rb[q].y; fb[4*q+2] = rb[q].z; fb[4*q+3] = rb[q].w;
        }
        __half ha[16], la[16], hb[16], lb[16];
        #pragma unroll
        for (int i = 0; i < 16; i++) {
            ha[i] = __float2half_rn(fa[i]);
            la[i] = __float2half_rn(fa[i] - __half2float(ha[i]));
            hb[i] = __float2half_rn(fb[i]);
            lb[i] = __float2half_rn(fb[i] - __half2float(hb[i]));
        }
        uint4 u;
        #pragma unroll
        for (int g = 0; g < 2; g++) {   // halves 0-7 and 8-15
            const uint32_t o = base + soff + (uint32_t)g * 16;
            u = make_uint4(packh(ha[8*g+0],ha[8*g+1]), packh(ha[8*g+2],ha[8*g+3]),
                           packh(ha[8*g+4],ha[8*g+5]), packh(ha[8*g+6],ha[8*g+7]));
            *(uint4*)(smem + 0 * TILE_B + o) = u;
            u = make_uint4(packh(la[8*g+0],la[8*g+1]), packh(la[8*g+2],la[8*g+3]),
                           packh(la[8*g+4],la[8*g+5]), packh(la[8*g+6],la[8*g+7]));
            *(uint4*)(smem + 1 * TILE_B + o) = u;
            u = make_uint4(packh(hb[8*g+0],hb[8*g+1]), packh(hb[8*g+2],hb[8*g+3]),
                           packh(hb[8*g+4],hb[8*g+5]), packh(hb[8*g+6],hb[8*g+7]));
            *(uint4*)(smem + 2 * TILE_B + o) = u;
            u = make_uint4(packh(lb[8*g+0],lb[8*g+1]), packh(lb[8*g+2],lb[8*g+3]),
                           packh(lb[8*g+4],lb[8*g+5]), packh(lb[8*g+6],lb[8*g+7]));
            *(uint4*)(smem + 3 * TILE_B + o) = u;
        }
    };

    const uint32_t aoff = (uint32_t)(wm * 64 + (lane & 15)) * PITCH_B + ((lane >> 4) * 16);
    const uint32_t boff = (uint32_t)(wn * 32 + (lane & 7) + ((lane & 16) ? 8 : 0)) * PITCH_B
                        + (((lane >> 3) & 1) * 16);

    const int nk = K >> 5;
    ldg_stage(0);
    sts_stage(0);
    __syncthreads();

    for (int kt = 0; kt < nk; kt++) {
        if (kt + 1 < nk) ldg_stage(kt + 1);

        const uint32_t stg = (uint32_t)(kt & 1) * 4 * TILE_B;
        const uint32_t aAh = sb + stg + 0 * TILE_B;
        const uint32_t aAl = sb + stg + 1 * TILE_B;
        const uint32_t aBh = sb + stg + 2 * TILE_B;
        const uint32_t aBl = sb + stg + 3 * TILE_B;

        #pragma unroll
        for (int ks = 0; ks < 2; ks++) {
            uint32_t ah[4][4], al[4][4], bh[4][2], bl[4][2];
            #pragma unroll
            for (int mf = 0; mf < 4; mf++) {
                LDSM4(ah[mf], aAh + aoff + (uint32_t)mf * 16 * PITCH_B + ks * 32);
                LDSM4(al[mf], aAl + aoff + (uint32_t)mf * 16 * PITCH_B + ks * 32);
            }
            #pragma unroll
            for (int p = 0; p < 2; p++) {
                uint32_t r[4];
                LDSM4(r, aBh + boff + (uint32_t)p * 16 * PITCH_B + ks * 32);
                bh[2*p][0] = r[0]; bh[2*p][1] = r[1];
                bh[2*p+1][0] = r[2]; bh[2*p+1][1] = r[3];
                LDSM4(r, aBl + boff + (uint32_t)p * 16 * PITCH_B + ks * 32);
                bl[2*p][0] = r[0]; bl[2*p][1] = r[1];
                bl[2*p+1][0] = r[2]; bl[2*p+1][1] = r[3];
            }
            #pragma unroll
            for (int mf = 0; mf < 4; mf++)
                #pragma unroll
                for (int nf = 0; nf < 4; nf++) {
                    MMA16816(acc[mf][nf], ah[mf], bh[nf]);
                    MMA16816(acc[mf][nf], ah[mf], bl[nf]);
                    MMA16816(acc[mf][nf], al[mf], bh[nf]);
                }
        }

        if (kt + 1 < nk) {
            sts_stage((kt + 1) & 1);
            __syncthreads();
        }
    }

    // ---- epilogue: tanh(x + bias), direct global stores ----
    const int er = bm + wm * 64 + (lane >> 2);
    const int ec = bn + wn * 32 + (lane & 3) * 2;
    #pragma unroll
    for (int mf = 0; mf < 4; mf++)
        #pragma unroll
        for (int nf = 0; nf < 4; nf++) {
            const int r = er + mf * 16;
            const int c = ec + nf * 8;
            const float b0 = __ldg(&bias[c]), b1 = __ldg(&bias[c + 1]);
            float v0 = tanhf(acc[mf][nf][0] + b0);
            float v1 = tanhf(acc[mf][nf][1] + b1);
            float v2 = tanhf(acc[mf][nf][2] + b0);
            float v3 = tanhf(acc[mf][nf][3] + b1);
            *(float2*)&C[(size_t)r * N + c]       = make_float2(v0, v1);
            *(float2*)&C[(size_t)(r + 8) * N + c] = make_float2(v2, v3);
        }
}

// ===========================================================================
// K3: plain fp16 NT GEMM via mma.sync (operands already fp16), fp32 accum.
// C[M,N] = A[M,K] @ B[N,K]^T.  cp.async double-buffered loader.
// ===========================================================================
__global__ __launch_bounds__(256) void mma_nt_h(
    const __half* __restrict__ A, const __half* __restrict__ B,
    float* __restrict__ C, int M, int N, int K)
{
    extern __shared__ char smem[];
    const int tid  = threadIdx.x;
    const int lane = tid & 31;
    const int wid  = tid >> 5;
    const int wm   = wid >> 2;
    const int wn   = wid & 3;
    const int bm   = blockIdx.y * 128;
    const int bn   = blockIdx.x * 128;
    const uint32_t sb = smem_u32(smem);

    float acc[4][4][4];
    #pragma unroll
    for (int i = 0; i < 4; i++)
        #pragma unroll
        for (int j = 0; j < 4; j++)
            #pragma unroll
            for (int k = 0; k < 4; k++) acc[i][j][k] = 0.f;

    const __half* srcs[2] = { A, B };
    const int r0s[2] = { bm, bn };
    const int lrow0 = tid >> 2;
    const int lcc   = (tid & 3) * 16;

    auto prefetch = [&](int kt, int stage) {
        const int k0b = kt * 64;
        #pragma unroll
        for (int t = 0; t < 2; t++) {
            const uint32_t db = sb + (uint32_t)(stage * 2 + t) * TILE_B;
            const char* s = (const char*)srcs[t];
            #pragma unroll
            for (int it = 0; it < 2; it++) {
                const int row = lrow0 + it * 64;
                const uint32_t d = db + (uint32_t)row * PITCH_B + lcc;
                const char* g = s + ((size_t)(r0s[t] + row) * K) * 2 + k0b + lcc;
                CP_ASYNC16(d, g);
            }
        }
    };

    const uint32_t aoff = (uint32_t)(wm * 64 + (lane & 15)) * PITCH_B + ((lane >> 4) * 16);
    const uint32_t boff = (uint32_t)(wn * 32 + (lane & 7) + ((lane & 16) ? 8 : 0)) * PITCH_B
                        + (((lane >> 3) & 1) * 16);

    const int nk = K >> 5;
    prefetch(0, 0);
    CP_COMMIT();

    for (int kt = 0; kt < nk; kt++) {
        if (kt + 1 < nk) { prefetch(kt + 1, (kt + 1) & 1); CP_COMMIT(); CP_WAIT(1); }
        else             { CP_WAIT(0); }
        __syncthreads();

        const uint32_t stg = (uint32_t)(kt & 1) * 2 * TILE_B;
        const uint32_t aA = sb + stg + 0 * TILE_B;
        const uint32_t aB = sb + stg + 1 * TILE_B;

        #pragma unroll
        for (int ks = 0; ks < 2; ks++) {
            uint32_t ah[4][4], bh[4][2];
            #pragma unroll
            for (int mf = 0; mf < 4; mf++)
                LDSM4(ah[mf], aA + aoff + (uint32_t)mf * 16 * PITCH_B + ks * 32);
            #pragma unroll
            for (int p = 0; p < 2; p++) {
                uint32_t r[4];
                LDSM4(r, aB + boff + (uint32_t)p * 16 * PITCH_B + ks * 32);
                bh[2*p][0] = r[0]; bh[2*p][1] = r[1];
                bh[2*p+1][0] = r[2]; bh[2*p+1][1] = r[3];
            }
            #pragma unroll
            for (int mf = 0; mf < 4; mf++)
                #pragma unroll
                for (int nf = 0; nf < 4; nf++)
                    MMA16816(acc[mf][nf], ah[mf], bh[nf]);
        }
        __syncthreads();
    }

    const int er = bm + wm * 64 + (lane >> 2);
    const int ec = bn + wn * 32 + (lane & 3) * 2;
    #pragma unroll
    for (int mf = 0; mf < 4; mf++)
        #pragma unroll
        for (int nf = 0; nf < 4; nf++) {
            const int r = er + mf * 16;
            const int c = ec + nf * 8;
            *(float2*)&C[(size_t)r * N + c]       = make_float2(acc[mf][nf][0], acc[mf][nf][1]);
            *(float2*)&C[(size_t)(r + 8) * N + c] = make_float2(acc[mf][nf][2], acc[mf][nf][3]);
        }
}

// ---------------------------------------------------------------------------
// Per-batch select: normalize t row, argmax_j (t . v_j)/||v_j|| (pure fp32 —
// no selection-flip risk), emit fp16 t_norm and fp16 v_sel_norm.
// ---------------------------------------------------------------------------
__global__ __launch_bounds__(256) void select_kernel(const float* __restrict__ vis)
{
    __shared__ float ts[DD];
    __shared__ float s_sim[8];
    __shared__ int   s_j[8];
    __shared__ float s_nn[8];
    __shared__ float s_scale;
    __shared__ int   s_bj;

    const int b    = blockIdx.x;
    const int tid  = threadIdx.x;
    const int lane = tid & 31;
    const int w    = tid >> 5;

    // ---- load + normalize t row ----
    const float* trow = g_t + (size_t)b * DD;
    float4 tv = ((const float4*)trow)[tid];
    float ss = tv.x * tv.x + tv.y * tv.y + tv.z * tv.z + tv.w * tv.w;
    #pragma unroll
    for (int o = 16; o; o >>= 1) ss += __shfl_xor_sync(0xffffffffu, ss, o);
    if (lane == 0) s_nn[w] = ss;
    __syncthreads();
    if (tid == 0) {
        float tot = 0.f;
        #pragma unroll
        for (int i = 0; i < 8; i++) tot += s_nn[i];
        s_scale = 1.0f / fmaxf(sqrtf(tot), 1e-12f);
    }
    __syncthreads();
    {
        const float inv = s_scale;
        tv.x *= inv; tv.y *= inv; tv.z *= inv; tv.w *= inv;
        ((float4*)ts)[tid] = tv;
        __half2* H = (__half2*)(g_t_h + (size_t)b * DD);
        H[2 * tid]     = __halves2half2(__float2half_rn(tv.x), __float2half_rn(tv.y));
        H[2 * tid + 1] = __halves2half2(__float2half_rn(tv.z), __float2half_rn(tv.w));
    }
    __syncthreads();

    // ---- stream v[b] (evict-first), fused dot + norm^2, warp-strided ----
    float best = -1e30f;
    int   bj   = 0x7fffffff;
    float bnn  = 1.0f;
    const float4* tsv = (const float4*)ts;

    for (int j = w; j < NN; j += 8) {
        const float4* vr = (const float4*)(vis + ((size_t)b * NN + j) * DD);
        float dot = 0.f, nn = 0.f;
        #pragma unroll
        for (int i = 0; i < 8; i++) {
            float4 x  = __ldcs(&vr[lane + 32 * i]);
            float4 tt = tsv[lane + 32 * i];
            dot += x.x * tt.x; dot += x.y * tt.y; dot += x.z * tt.z; dot += x.w * tt.w;
            nn  += x.x * x.x;  nn  += x.y * x.y;  nn  += x.z * x.z;  nn  += x.w * x.w;
        }
        #pragma unroll
        for (int o = 16; o; o >>= 1) {
            dot += __shfl_xor_sync(0xffffffffu, dot, o);
            nn  += __shfl_xor_sync(0xffffffffu, nn, o);
        }
        const float sim = dot * rsqrtf(fmaxf(nn, 1e-24f));
        if (sim > best) { best = sim; bj = j; bnn = nn; }
    }
    if (lane == 0) { s_sim[w] = best; s_j[w] = bj; s_nn[w] = bnn; }
    __syncthreads();

    if (tid == 0) {
        float bs = s_sim[0]; int bjj = s_j[0]; float bn = s_nn[0];
        #pragma unroll
        for (int i = 1; i < 8; i++) {
            if (s_sim[i] > bs || (s_sim[i] == bs && s_j[i] < bjj)) {
                bs = s_sim[i]; bjj = s_j[i]; bn = s_nn[i];
            }
        }
        s_bj = bjj;
        s_scale = 1.0f / fmaxf(sqrtf(bn), 1e-12f);
    }
    __syncthreads();

    // ---- write fp16 normalized selected row (re-read = L2 hit) ----
    const int   jb = s_bj;
    const float sc = s_scale;
    const float4* vrb = (const float4*)(vis + ((size_t)b * NN + jb) * DD);
    float4 x4 = vrb[tid];
    __half2* H = (__half2*)(g_v_h + (size_t)b * DD);
    H[2 * tid]     = __halves2half2(__float2half_rn(x4.x * sc), __float2half_rn(x4.y * sc));
    H[2 * tid + 1] = __halves2half2(__float2half_rn(x4.z * sc), __float2half_rn(x4.w * sc));
}

// ---------------------------------------------------------------------------
// Launch
// ---------------------------------------------------------------------------
extern "C" void kernel_launch(void* const* d_in, const int* in_sizes, int n_in,
                              void* d_out, int out_size)
{
    const float* vis  = nullptr;
    const float* txt  = nullptr;
    const float* W    = nullptr;
    const float* bias = nullptr;
    for (int i = 0; i < n_in; i++) {
        const long long s = in_sizes[i];
        if      (s == (long long)BB * NN * DD) vis  = (const float*)d_in[i];
        else if (s == (long long)BB * DC)      txt  = (const float*)d_in[i];
        else if (s == (long long)DD * DC)      W    = (const float*)d_in[i];
        else if (s == (long long)DD)           bias = (const float*)d_in[i];
    }
    float* out = (float*)d_out;

    float *t_ptr;
    __half *th, *vh;
    cudaGetSymbolAddress((void**)&t_ptr, g_t);
    cudaGetSymbolAddress((void**)&th,  g_t_h);
    cudaGetSymbolAddress((void**)&vh,  g_v_h);

    const int smem4 = 2 * 4 * TILE_B;   // 81920 (K1: Ah,Al,Bh,Bl x 2 stages)
    const int smem2 = 2 * 2 * TILE_B;   // 40960 (K3: A,B x 2 stages)
    cudaFuncSetAttribute(mma_nt_f32, cudaFuncAttributeMaxDynamicSharedMemorySize, smem4);
    cudaFuncSetAttribute(mma_nt_h,   cudaFuncAttributeMaxDynamicSharedMemorySize, smem2);

    // K1: t = tanh(txt @ W^T + b)  [2048,1024], K=512  (fused fp32->hi/lo split)
    {
        dim3 grid(DD / 128, BB / 128);
        mma_nt_f32<<<grid, 256, smem4>>>(txt, W, bias, t_ptr, BB, DD, DC);
    }
    // K2: normalize t, fp32 argmax over patches, emit fp16 operands for K3
    select_kernel<<<BB, 256>>>(vis);
    // K3: out = t_norm @ v_sel^T  [2048,2048], K=1024  (fp16, err ~3e-4 global)
    {
        dim3 grid(BB / 128, BB / 128);
        mma_nt_h<<<grid, 256, smem2>>>(th, vh, out, BB, BB, DD);
    }
}